// round 4
// baseline (speedup 1.0000x reference)
#include <cuda_runtime.h>
#include <math.h>
#include <stdint.h>

#define BATCH 32
#define TLEN  512
#define INDIM 128
#define RES   2048
#define OUTD  64
#define NWIN  128
#define MROWS (BATCH*NWIN)   /* 4096  reservoir rows (b,w) */
#define NROWS (BATCH*TLEN)   /* 16384 time rows (b,t)      */

/* ---------------- scratch (device globals; no allocations) ---------------- */
__device__ float g_inproj[NROWS * RES];    /* input @ W_in          128 MB */
__device__ float g_S0[MROWS * RES];        /* state ping             32 MB */
__device__ float g_S1[MROWS * RES];        /* state pong             32 MB */
__device__ float g_rs[NROWS * RES];        /* reservoir states      128 MB */
__device__ float g_A[BATCH * TLEN * TLEN]; /* gram matrices          32 MB */
__device__ float g_LT[BATCH * TLEN * TLEN];/* L transposed           32 MB */
__device__ float g_Z[BATCH * TLEN * OUTD]; /* solve result            4 MB */
__device__ float g_WresT[RES * RES];       /* W_res transposed       16 MB */
__device__ float g_WinT[RES * INDIM];      /* W_in transposed         1 MB */

/* ====================== helpers ====================== */
/* m16n8k8 tf32 mma: D += A*B, row.col */
__device__ __forceinline__ void mma1688(float* d, const uint32_t* a, const uint32_t* b) {
    asm volatile(
        "mma.sync.aligned.m16n8k8.row.col.f32.tf32.tf32.f32 "
        "{%0,%1,%2,%3},{%4,%5,%6,%7},{%8,%9},{%0,%1,%2,%3};"
        : "+f"(d[0]), "+f"(d[1]), "+f"(d[2]), "+f"(d[3])
        : "r"(a[0]), "r"(a[1]), "r"(a[2]), "r"(a[3]), "r"(b[0]), "r"(b[1]));
}

__device__ __forceinline__ float2 split2(float f) {
    float hi = __uint_as_float(__float_as_uint(f) & 0xFFFFE000u);
    return make_float2(hi, f - hi);
}

/* ============ generic tf32x3 GEMM kernel (mma.sync HMMA path) =============
   C[row0+i][col0+j] = sum_k A[row0+i][k] * B[col0+j][k]   (A·B^T, K-major)
   mode 0: reservoir step  (A=Sold, B=WresT, fused leaky-sin epilogue)
   mode 1: gram, symmetric (A=B=rs batch slice; lower tiles only, mirrored)
   mode 2: inproj          (A=input, B=WinT, plain store)
   SMEM: 3 stages x (Apack + Bpack), each [128][36] float2 (hi,lo packed).  */
#define PAD2 36
#define STAGE_F2 (128 * PAD2)              /* float2 per operand region */
#define SMEM_DYN (3 * 2 * STAGE_F2 * 8)    /* 221184 B */

__global__ __launch_bounds__(512, 1) void tc_kernel(
    int mode, const float* __restrict__ Xin, int s, int flip,
    const float* __restrict__ lam)
{
    extern __shared__ float2 sm2[];

    const int tid = threadIdx.x;
    const int wid = tid >> 5, lane = tid & 31;
    const int gid = lane >> 2, tig = lane & 3;
    const int warpM = wid >> 2, warpN = wid & 3;
    const int rowBase = warpM * 32, colBase = warpN * 32;

    int row0, col0, gti = 0, gtj = 0;
    if (mode == 1) {
        int x = blockIdx.x, ti = 0;
        while ((ti + 1) * (ti + 2) / 2 <= x) ti++;
        gti = ti; gtj = x - ti * (ti + 1) / 2;
        row0 = gti * 128; col0 = gtj * 128;
    } else {
        row0 = blockIdx.y * 128; col0 = blockIdx.x * 128;
    }

    const float* Ab; const float* Bb; int K;
    if (mode == 0)      { Ab = flip ? g_S1 : g_S0; Bb = g_WresT; K = RES; }
    else if (mode == 1) { const float* base = g_rs + (size_t)blockIdx.z * TLEN * RES;
                          Ab = base; Bb = base; K = RES; }
    else                { Ab = Xin; Bb = g_WinT; K = INDIM; }
    const int nIter = K >> 5;

    float acc[2][4][4] = {};
    float4 rA[2], rB[2];

    const int ldr = tid >> 3, ldc = (tid & 7) * 4;   /* loader row / col(first of 4) */

    auto ldg_chunk = [&](int it) {
        const int k0 = it << 5;
        #pragma unroll
        for (int q = 0; q < 2; q++) {
            int r = ldr + q * 64;
            rA[q] = *(const float4*)&Ab[(size_t)(row0 + r) * K + k0 + ldc];
            rB[q] = *(const float4*)&Bb[(size_t)(col0 + r) * K + k0 + ldc];
        }
    };
    auto sts_chunk = [&](int stage) {
        float2* Ap = sm2 + (size_t)stage * (2 * STAGE_F2);
        float2* Bp = Ap + STAGE_F2;
        #pragma unroll
        for (int q = 0; q < 2; q++) {
            int r = ldr + q * 64;
            int off = r * PAD2 + ldc;
            Ap[off + 0] = split2(rA[q].x);
            Ap[off + 1] = split2(rA[q].y);
            Ap[off + 2] = split2(rA[q].z);
            Ap[off + 3] = split2(rA[q].w);
            Bp[off + 0] = split2(rB[q].x);
            Bp[off + 1] = split2(rB[q].y);
            Bp[off + 2] = split2(rB[q].z);
            Bp[off + 3] = split2(rB[q].w);
        }
    };

    /* prologue */
    ldg_chunk(0);
    sts_chunk(0);
    if (nIter > 1) ldg_chunk(1);
    __syncthreads();

    for (int it = 0; it < nIter; ++it) {
        if (it + 1 < nIter) sts_chunk((it + 1) % 3);
        if (it + 2 < nIter) ldg_chunk(it + 2);

        const float2* Ap = sm2 + (size_t)(it % 3) * (2 * STAGE_F2);
        const float2* Bp = Ap + STAGE_F2;
        #pragma unroll
        for (int k8 = 0; k8 < 4; k8++) {
            const int kk = k8 * 8 + tig;
            uint32_t ah[2][4], al[2][4], bh[4][2], bl[4][2];
            #pragma unroll
            for (int mt = 0; mt < 2; mt++) {
                int r = rowBase + mt * 16 + gid;
                float2 p0 = Ap[r * PAD2 + kk];
                float2 p1 = Ap[(r + 8) * PAD2 + kk];
                float2 p2 = Ap[r * PAD2 + kk + 4];
                float2 p3 = Ap[(r + 8) * PAD2 + kk + 4];
                ah[mt][0] = __float_as_uint(p0.x); al[mt][0] = __float_as_uint(p0.y);
                ah[mt][1] = __float_as_uint(p1.x); al[mt][1] = __float_as_uint(p1.y);
                ah[mt][2] = __float_as_uint(p2.x); al[mt][2] = __float_as_uint(p2.y);
                ah[mt][3] = __float_as_uint(p3.x); al[mt][3] = __float_as_uint(p3.y);
            }
            #pragma unroll
            for (int nt = 0; nt < 4; nt++) {
                int n = colBase + nt * 8 + gid;
                float2 q0 = Bp[n * PAD2 + kk];
                float2 q1 = Bp[n * PAD2 + kk + 4];
                bh[nt][0] = __float_as_uint(q0.x); bl[nt][0] = __float_as_uint(q0.y);
                bh[nt][1] = __float_as_uint(q1.x); bl[nt][1] = __float_as_uint(q1.y);
            }
            #pragma unroll
            for (int mt = 0; mt < 2; mt++)
                #pragma unroll
                for (int nt = 0; nt < 4; nt++) {
                    mma1688(acc[mt][nt], ah[mt], bh[nt]);
                    mma1688(acc[mt][nt], ah[mt], bl[nt]);
                    mma1688(acc[mt][nt], al[mt], bh[nt]);
                }
        }
        __syncthreads();
    }

    /* -------------------- epilogue (register -> global) -------------------- */
    float regc = 0.f;
    if (mode == 1) { float l = lam[0]; regc = log1pf(expf(l)); }
    const float* Sold = flip ? g_S1 : g_S0;
    float* Snew = flip ? g_S0 : g_S1;

    #pragma unroll
    for (int mt = 0; mt < 2; mt++)
        #pragma unroll
        for (int nt = 0; nt < 4; nt++)
            #pragma unroll
            for (int h = 0; h < 2; h++) {
                int grow = row0 + rowBase + mt * 16 + gid + h * 8;
                int col = col0 + colBase + nt * 8 + tig * 2;
                float cx = acc[mt][nt][h * 2 + 0];
                float cy = acc[mt][nt][h * 2 + 1];
                if (mode == 0) {
                    int b = grow >> 7, w = grow & 127;
                    int t = 4 * w + s - 2;
                    float2 so = *(const float2*)&Sold[(size_t)grow * RES + col];
                    float2 u = make_float2(0.f, 0.f);
                    if (t >= 0) u = *(const float2*)&g_inproj[((size_t)(b << 9) + t) * RES + col];
                    float2 v;
                    v.x = 0.7f * so.x + 0.3f * sinf(cx + u.x);
                    v.y = 0.7f * so.y + 0.3f * sinf(cy + u.y);
                    *(float2*)&Snew[(size_t)grow * RES + col] = v;
                    if (s >= 2) *(float2*)&g_rs[((size_t)(b << 9) + t) * RES + col] = v;
                } else if (mode == 1) {
                    float* Abm = g_A + (size_t)blockIdx.z * TLEN * TLEN;
                    float2 v;
                    v.x = cx + 1.0f + ((grow == col + 0) ? regc : 0.f);
                    v.y = cy + 1.0f + ((grow == col + 1) ? regc : 0.f);
                    *(float2*)&Abm[(size_t)grow * TLEN + col] = v;
                    if (gti != gtj) {            /* mirror to upper triangle */
                        Abm[(size_t)(col + 0) * TLEN + grow] = v.x;
                        Abm[(size_t)(col + 1) * TLEN + grow] = v.y;
                    }
                } else {
                    float2 v = make_float2(cx, cy);
                    *(float2*)&g_inproj[(size_t)grow * RES + col] = v;
                }
            }
}

/* ================= transpose: dst[c][r] = src[r][c] ======================= */
__global__ void transpose_kernel(const float* __restrict__ src, int rows, int cols, int which)
{
    float* dst = which ? g_WinT : g_WresT;
    __shared__ float t[32][33];
    int c0 = blockIdx.x * 32, r0 = blockIdx.y * 32;
    for (int j = threadIdx.y; j < 32; j += 8)
        t[j][threadIdx.x] = src[(size_t)(r0 + j) * cols + c0 + threadIdx.x];
    __syncthreads();
    for (int j = threadIdx.y; j < 32; j += 8)
        dst[(size_t)(c0 + j) * rows + r0 + threadIdx.x] = t[threadIdx.x][j];
}

/* ====== transpose Cholesky factors: g_LT[b][j][i] = g_A[b][i][j] ========== */
__global__ void transL_kernel()
{
    const int b = blockIdx.z;
    const float* src = g_A + (size_t)b * TLEN * TLEN;
    float* dst = g_LT + (size_t)b * TLEN * TLEN;
    __shared__ float t[32][33];
    int c0 = blockIdx.x * 32, r0 = blockIdx.y * 32;
    for (int j = threadIdx.y; j < 32; j += 8)
        t[j][threadIdx.x] = src[(size_t)(r0 + j) * TLEN + c0 + threadIdx.x];
    __syncthreads();
    for (int j = threadIdx.y; j < 32; j += 8)
        dst[(size_t)(c0 + j) * TLEN + r0 + threadIdx.x] = t[threadIdx.x][j];
}

/* =================== step s=0 (state was zero) ============================ */
__global__ __launch_bounds__(256) void init0_kernel()
{
    int idx = blockIdx.x * 256 + threadIdx.x;
    int row = idx >> 11, qq = idx & 2047;
    int b = row >> 7, w = row & 127;
    int t = 4 * w - 2;
    float v = 0.f;
    if (t >= 0) v = 0.3f * sinf(g_inproj[((size_t)(b << 9) + t) * RES + qq]);
    g_S0[idx] = v;
}

/* ============ blocked Cholesky, NB=64 ===================================== */
__global__ __launch_bounds__(256) void chol_panel_kernel(int p)
{
    const int b = blockIdx.x;
    float* Ab = g_A + (size_t)b * TLEN * TLEN;
    const int jb = p * 64;
    __shared__ float L11[64][65];
    const int tid = threadIdx.x;
    for (int idx = tid; idx < 64 * 64; idx += 256) {
        int r = idx >> 6, c = idx & 63;
        L11[r][c] = Ab[(jb + r) * TLEN + jb + c];
    }
    __syncthreads();
    for (int k = 0; k < 64; k++) {
        if (tid == 0) L11[k][k] = sqrtf(L11[k][k]);
        __syncthreads();
        if (tid > k && tid < 64) L11[tid][k] /= L11[k][k];
        __syncthreads();
        for (int idx = tid; idx < 64 * 64; idx += 256) {
            int r = idx >> 6, c = idx & 63;
            if (r > k && c > k && c <= r) L11[r][c] -= L11[r][k] * L11[c][k];
        }
        __syncthreads();
    }
    for (int idx = tid; idx < 64 * 64; idx += 256) {
        int r = idx >> 6, c = idx & 63;
        if (c <= r) Ab[(jb + r) * TLEN + jb + c] = L11[r][c];
    }
    __syncthreads();
    const int m = TLEN - jb - 64;
    for (int r = tid; r < m; r += 256) {
        int i = jb + 64 + r;
        float a[64];
        #pragma unroll
        for (int c = 0; c < 64; c++) a[c] = Ab[i * TLEN + jb + c];
        #pragma unroll
        for (int k = 0; k < 64; k++) {
            float sv = a[k];
            #pragma unroll
            for (int q = 0; q < k; q++) sv -= a[q] * L11[k][q];
            a[k] = sv / L11[k][k];
        }
        #pragma unroll
        for (int c = 0; c < 64; c++) Ab[i * TLEN + jb + c] = a[c];
    }
}

__global__ __launch_bounds__(256) void chol_update_kernel(int p)
{
    const int jb = p * 64 + 64;
    int idx = blockIdx.x;
    int ti = 0;
    while ((ti + 1) * (ti + 2) / 2 <= idx) ti++;
    int tj = idx - ti * (ti + 1) / 2;
    const int b = blockIdx.y;
    float* Ab = g_A + (size_t)b * TLEN * TLEN;
    const int r0 = jb + ti * 64, c0 = jb + tj * 64;
    __shared__ float La[64][65], Lb[64][65];
    const int tid = threadIdx.x;
    for (int q = tid; q < 64 * 64; q += 256) {
        int r = q >> 6, c = q & 63;
        La[r][c] = Ab[(r0 + r) * TLEN + p * 64 + c];
        Lb[r][c] = Ab[(c0 + r) * TLEN + p * 64 + c];
    }
    __syncthreads();
    const int tx = tid & 15, ty = tid >> 4;
    float acc[4][4] = {};
    #pragma unroll
    for (int k = 0; k < 64; k++) {
        float ar[4], bc[4];
        #pragma unroll
        for (int i = 0; i < 4; i++) ar[i] = La[ty * 4 + i][k];
        #pragma unroll
        for (int j = 0; j < 4; j++) bc[j] = Lb[tx * 4 + j][k];
        #pragma unroll
        for (int i = 0; i < 4; i++)
            #pragma unroll
            for (int j = 0; j < 4; j++)
                acc[i][j] += ar[i] * bc[j];
    }
    #pragma unroll
    for (int i = 0; i < 4; i++)
        #pragma unroll
        for (int j = 0; j < 4; j++)
            Ab[(r0 + ty * 4 + i) * TLEN + c0 + tx * 4 + j] -= acc[i][j];
}

/* ============ triangular solves, 64 RHS in registers ====================== */
__global__ __launch_bounds__(512) void solve_kernel(const float* __restrict__ Y)
{
    const int b = blockIdx.x;
    const int i = threadIdx.x;
    const float* __restrict__ Ab = g_A + (size_t)b * TLEN * TLEN;
    const float* __restrict__ Lt = g_LT + (size_t)b * TLEN * TLEN;
    float acc[OUTD];
    #pragma unroll
    for (int o = 0; o < OUTD; o++) acc[o] = Y[((size_t)b * TLEN + i) * OUTD + o];
    __shared__ float zrow[OUTD];
    /* forward: L w = y   (coalesced via LT: LT[j][i] = L[i][j]) */
    for (int j = 0; j < TLEN; j++) {
        if (i == j) {
            float dinv = 1.f / Ab[j * TLEN + j];
            #pragma unroll
            for (int o = 0; o < OUTD; o++) { acc[o] *= dinv; zrow[o] = acc[o]; }
        }
        __syncthreads();
        if (i > j) {
            float lij = Lt[j * TLEN + i];
            #pragma unroll
            for (int o = 0; o < OUTD; o++) acc[o] -= lij * zrow[o];
        }
        __syncthreads();
    }
    /* backward: L^T z = w   (row j of L, coalesced) */
    for (int j = TLEN - 1; j >= 0; j--) {
        if (i == j) {
            float dinv = 1.f / Ab[j * TLEN + j];
            #pragma unroll
            for (int o = 0; o < OUTD; o++) { acc[o] *= dinv; zrow[o] = acc[o]; }
        }
        __syncthreads();
        if (i < j) {
            float lji = Ab[j * TLEN + i];
            #pragma unroll
            for (int o = 0; o < OUTD; o++) acc[o] -= lji * zrow[o];
        }
        __syncthreads();
    }
    #pragma unroll
    for (int o = 0; o < OUTD; o++) g_Z[((size_t)b * TLEN + i) * OUTD + o] = acc[o];
}

/* ============ W = Xb^T Z  (2048 x 64, K=512) ============================== */
__global__ __launch_bounds__(256) void wout_kernel(float* __restrict__ out)
{
    const int b = blockIdx.y;
    const float* __restrict__ X = g_rs + (size_t)b * TLEN * RES;
    const float* __restrict__ Zb = g_Z + (size_t)b * TLEN * OUTD;
    const int d0 = blockIdx.x * 128;
    __shared__ float As2[16][132];
    __shared__ float Bs2[16][68];
    const int tid = threadIdx.x;
    const int lr = tid >> 4, lc = (tid & 15) * 4;
    const int ty = tid >> 4, tx = tid & 15;
    float acc[8][4] = {};
    for (int k0 = 0; k0 < TLEN; k0 += 16) {
        *(float4*)&As2[lr][lc]      = *(const float4*)&X[(size_t)(k0 + lr) * RES + d0 + lc];
        *(float4*)&As2[lr][lc + 64] = *(const float4*)&X[(size_t)(k0 + lr) * RES + d0 + lc + 64];
        *(float4*)&Bs2[lr][lc]      = *(const float4*)&Zb[(k0 + lr) * OUTD + lc];
        __syncthreads();
        #pragma unroll
        for (int k = 0; k < 16; k++) {
            float fa[8], fb[4];
            *(float4*)&fa[0] = *(const float4*)&As2[k][ty * 8];
            *(float4*)&fa[4] = *(const float4*)&As2[k][ty * 8 + 4];
            *(float4*)&fb[0] = *(const float4*)&Bs2[k][tx * 4];
            #pragma unroll
            for (int i = 0; i < 8; i++)
                #pragma unroll
                for (int j = 0; j < 4; j++)
                    acc[i][j] += fa[i] * fb[j];
        }
        __syncthreads();
    }
    #pragma unroll
    for (int i = 0; i < 8; i++)
        #pragma unroll
        for (int j = 0; j < 4; j++)
            out[((size_t)b * RES + d0 + ty * 8 + i) * OUTD + tx * 4 + j] = acc[i][j];
}

__global__ void bias_kernel(float* __restrict__ out)
{
    const int b = blockIdx.x, o = threadIdx.x;
    float s = 0.f;
    for (int n = 0; n < TLEN; n++) s += g_Z[((size_t)b * TLEN + n) * OUTD + o];
    out[(size_t)BATCH * RES * OUTD + b * OUTD + o] = s;
}

/* ======================= launch ======================= */
extern "C" void kernel_launch(void* const* d_in, const int* in_sizes, int n_in,
                              void* d_out, int out_size)
{
    const float* input  = (const float*)d_in[0];
    const float* target = (const float*)d_in[1];
    const float* W_res  = (const float*)d_in[2];
    const float* W_in   = (const float*)d_in[3];
    const float* lam    = (const float*)d_in[4];
    float* out = (float*)d_out;

    cudaFuncSetAttribute(tc_kernel, cudaFuncAttributeMaxDynamicSharedMemorySize, SMEM_DYN);

    /* transposes for K-major A·B^T form */
    transpose_kernel<<<dim3(RES / 32, RES / 32), dim3(32, 8)>>>(W_res, RES, RES, 0);
    transpose_kernel<<<dim3(RES / 32, INDIM / 32), dim3(32, 8)>>>(W_in, INDIM, RES, 1);

    /* 1. input projection (tensor) */
    tc_kernel<<<dim3(RES / 128, NROWS / 128), 512, SMEM_DYN>>>(2, input, 0, 0, nullptr);

    /* 2. reservoir */
    init0_kernel<<<(MROWS * RES) / 256, 256>>>();
    int flip = 0;
    for (int s = 1; s <= 5; s++) {
        tc_kernel<<<dim3(RES / 128, MROWS / 128), 512, SMEM_DYN>>>(0, nullptr, s, flip, nullptr);
        flip ^= 1;
    }

    /* 3. gram (tensor, symmetric: 10 lower tiles) */
    tc_kernel<<<dim3(10, 1, BATCH), 512, SMEM_DYN>>>(1, nullptr, 0, 0, lam);

    /* 4. batched blocked Cholesky */
    for (int p = 0; p < 8; p++) {
        chol_panel_kernel<<<BATCH, 256>>>(p);
        if (p < 7) {
            int mt = 7 - p;
            chol_update_kernel<<<dim3(mt * (mt + 1) / 2, BATCH), 256>>>(p);
        }
    }

    /* 4b. transpose L for coalesced forward solve */
    transL_kernel<<<dim3(16, 16, BATCH), dim3(32, 8)>>>();

    /* 5. triangular solves */
    solve_kernel<<<BATCH, 512>>>(target);

    /* 6. readout */
    wout_kernel<<<dim3(RES / 128, BATCH), 256>>>(out);
    bias_kernel<<<BATCH, 64>>>(out);

    (void)in_sizes; (void)n_in; (void)out_size;
}

// round 5
// speedup vs baseline: 1.1659x; 1.1659x over previous
#include <cuda_runtime.h>
#include <math.h>
#include <stdint.h>

#define BATCH 32
#define TLEN  512
#define INDIM 128
#define RES   2048
#define OUTD  64
#define NWIN  128
#define MROWS (BATCH*NWIN)   /* 4096  reservoir rows (b,w) */
#define NROWS (BATCH*TLEN)   /* 16384 time rows (b,t)      */

/* ---------------- scratch (device globals; no allocations) ---------------- */
__device__ float g_inproj[NROWS * RES];    /* input @ W_in          128 MB */
__device__ float g_S0[MROWS * RES];        /* state ping             32 MB */
__device__ float g_S1[MROWS * RES];        /* state pong             32 MB */
__device__ float g_rs[NROWS * RES];        /* reservoir states      128 MB */
__device__ float g_A[BATCH * TLEN * TLEN]; /* gram matrices          32 MB */
__device__ float g_LT[BATCH * TLEN * TLEN];/* L transposed           32 MB */
__device__ float g_Z[BATCH * TLEN * OUTD]; /* solve result            4 MB */
__device__ float g_WresT[RES * RES];       /* W_res transposed       16 MB */
__device__ float g_WinT[RES * INDIM];      /* W_in transposed         1 MB */

/* ====================== helpers ====================== */
__device__ __forceinline__ uint32_t smem_u32(const void* p) {
    uint32_t a;
    asm("{ .reg .u64 t; cvta.to.shared.u64 t, %1; cvt.u32.u64 %0, t; }" : "=r"(a) : "l"(p));
    return a;
}

__device__ __forceinline__ void cpasync16(uint32_t dst, const void* src) {
    asm volatile("cp.async.cg.shared.global [%0], [%1], 16;" :: "r"(dst), "l"(src));
}
__device__ __forceinline__ void cp_commit() {
    asm volatile("cp.async.commit_group;" ::: "memory");
}
__device__ __forceinline__ void cp_wait1() {
    asm volatile("cp.async.wait_group 1;" ::: "memory");
}
__device__ __forceinline__ void cp_wait0() {
    asm volatile("cp.async.wait_group 0;" ::: "memory");
}

/* m16n8k8 tf32 mma: D += A*B, row.col */
__device__ __forceinline__ void mma1688(float* d, const uint32_t* a, const uint32_t* b) {
    asm volatile(
        "mma.sync.aligned.m16n8k8.row.col.f32.tf32.tf32.f32 "
        "{%0,%1,%2,%3},{%4,%5,%6,%7},{%8,%9},{%0,%1,%2,%3};"
        : "+f"(d[0]), "+f"(d[1]), "+f"(d[2]), "+f"(d[3])
        : "r"(a[0]), "r"(a[1]), "r"(a[2]), "r"(a[3]), "r"(b[0]), "r"(b[1]));
}

__device__ __forceinline__ void split_tf32(float f, uint32_t& hi, uint32_t& lo) {
    uint32_t u = __float_as_uint(f) & 0xFFFFE000u;
    hi = u;
    lo = __float_as_uint(f - __uint_as_float(u));
}

/* ============ generic tf32x3 GEMM kernel (mma.sync HMMA path) =============
   C[row0+i][col0+j] = sum_k A[row0+i][k] * B[col0+j][k]   (A·B^T, K-major)
   mode 0: reservoir step  (A=Sold, B=WresT, fused leaky-sin epilogue)
   mode 1: gram, symmetric (A=B=rs batch slice; lower tiles only, mirrored)
   mode 2: inproj          (A=input, B=WinT, plain store)                  */
#define TCPAD 36
#define SMEM_DYN (2 * 2 * 128 * TCPAD * 4)   /* 73728 B */

__global__ __launch_bounds__(512, 1) void tc_kernel(
    int mode, const float* __restrict__ Xin, int s, int flip,
    const float* __restrict__ lam)
{
    extern __shared__ float sm[];
    float* As = sm;                    /* [2][128][TCPAD] */
    float* Bs = sm + 2 * 128 * TCPAD;  /* [2][128][TCPAD] */
    const uint32_t As_u = smem_u32(As), Bs_u = smem_u32(Bs);

    const int tid = threadIdx.x;
    const int wid = tid >> 5, lane = tid & 31;
    const int gid = lane >> 2, tig = lane & 3;
    const int warpM = wid >> 2, warpN = wid & 3;
    const int rowBase = warpM * 32, colBase = warpN * 32;

    int row0, col0, gti = 0, gtj = 0;
    if (mode == 1) {
        int x = blockIdx.x, ti = 0;
        while ((ti + 1) * (ti + 2) / 2 <= x) ti++;
        gti = ti; gtj = x - ti * (ti + 1) / 2;
        row0 = gti * 128; col0 = gtj * 128;
    } else {
        row0 = blockIdx.y * 128; col0 = blockIdx.x * 128;
    }

    const float* Ab; const float* Bb; int K;
    if (mode == 0)      { Ab = flip ? g_S1 : g_S0; Bb = g_WresT; K = RES; }
    else if (mode == 1) { const float* base = g_rs + (size_t)blockIdx.z * TLEN * RES;
                          Ab = base; Bb = base; K = RES; }
    else                { Ab = Xin; Bb = g_WinT; K = INDIM; }
    const int nIter = K >> 5;

    float acc[2][4][4] = {};

    /* ---- chunk loader: 128 rows x 32 k into buf (A and B) ---- */
    auto load_chunk = [&](int it, int buf) {
        const int k0 = it << 5;
        #pragma unroll
        for (int q = 0; q < 2; q++) {
            int idx = tid + q * 512;             /* 1024 float4 slots */
            int r = idx >> 3, c4 = idx & 7;
            uint32_t soff = ((uint32_t)(buf * 128 + r) * TCPAD + c4 * 4) * 4;
            cpasync16(As_u + soff, &Ab[(size_t)(row0 + r) * K + k0 + c4 * 4]);
            cpasync16(Bs_u + soff, &Bb[(size_t)(col0 + r) * K + k0 + c4 * 4]);
        }
    };

    load_chunk(0, 0);
    cp_commit();

    for (int it = 0; it < nIter; ++it) {
        const int buf = it & 1;
        if (it + 1 < nIter) { load_chunk(it + 1, buf ^ 1); cp_commit(); cp_wait1(); }
        else                { cp_wait0(); }
        __syncthreads();

        const float* Ap = As + (size_t)buf * 128 * TCPAD;
        const float* Bp = Bs + (size_t)buf * 128 * TCPAD;
        #pragma unroll
        for (int k8 = 0; k8 < 4; k8++) {
            const int kk = k8 * 8 + tig;
            uint32_t ah[2][4], al[2][4], bh[4][2], bl[4][2];
            #pragma unroll
            for (int mt = 0; mt < 2; mt++) {
                int r = rowBase + mt * 16 + gid;
                split_tf32(Ap[r * TCPAD + kk],           ah[mt][0], al[mt][0]);
                split_tf32(Ap[(r + 8) * TCPAD + kk],     ah[mt][1], al[mt][1]);
                split_tf32(Ap[r * TCPAD + kk + 4],       ah[mt][2], al[mt][2]);
                split_tf32(Ap[(r + 8) * TCPAD + kk + 4], ah[mt][3], al[mt][3]);
            }
            #pragma unroll
            for (int nt = 0; nt < 4; nt++) {
                int n = colBase + nt * 8 + gid;
                split_tf32(Bp[n * TCPAD + kk],     bh[nt][0], bl[nt][0]);
                split_tf32(Bp[n * TCPAD + kk + 4], bh[nt][1], bl[nt][1]);
            }
            #pragma unroll
            for (int mt = 0; mt < 2; mt++)
                #pragma unroll
                for (int nt = 0; nt < 4; nt++) {
                    mma1688(acc[mt][nt], ah[mt], bh[nt]);
                    mma1688(acc[mt][nt], ah[mt], bl[nt]);
                    mma1688(acc[mt][nt], al[mt], bh[nt]);
                }
        }
        __syncthreads();
    }

    /* -------------------- epilogue (register -> global) -------------------- */
    float regc = 0.f;
    if (mode == 1) { float l = lam[0]; regc = log1pf(expf(l)); }
    const float* Sold = flip ? g_S1 : g_S0;
    float* Snew = flip ? g_S0 : g_S1;

    #pragma unroll
    for (int mt = 0; mt < 2; mt++)
        #pragma unroll
        for (int nt = 0; nt < 4; nt++)
            #pragma unroll
            for (int h = 0; h < 2; h++) {
                int grow = row0 + rowBase + mt * 16 + gid + h * 8;
                int col = col0 + colBase + nt * 8 + tig * 2;
                float cx = acc[mt][nt][h * 2 + 0];
                float cy = acc[mt][nt][h * 2 + 1];
                if (mode == 0) {
                    int b = grow >> 7, w = grow & 127;
                    int t = 4 * w + s - 2;
                    float2 so = *(const float2*)&Sold[(size_t)grow * RES + col];
                    float2 u = make_float2(0.f, 0.f);
                    if (t >= 0) u = *(const float2*)&g_inproj[((size_t)(b << 9) + t) * RES + col];
                    float2 v;
                    v.x = 0.7f * so.x + 0.3f * sinf(cx + u.x);
                    v.y = 0.7f * so.y + 0.3f * sinf(cy + u.y);
                    *(float2*)&Snew[(size_t)grow * RES + col] = v;
                    if (s >= 2) *(float2*)&g_rs[((size_t)(b << 9) + t) * RES + col] = v;
                } else if (mode == 1) {
                    float* Abm = g_A + (size_t)blockIdx.z * TLEN * TLEN;
                    float2 v;
                    v.x = cx + 1.0f + ((grow == col + 0) ? regc : 0.f);
                    v.y = cy + 1.0f + ((grow == col + 1) ? regc : 0.f);
                    *(float2*)&Abm[(size_t)grow * TLEN + col] = v;
                    if (gti != gtj) {            /* mirror to upper triangle */
                        Abm[(size_t)(col + 0) * TLEN + grow] = v.x;
                        Abm[(size_t)(col + 1) * TLEN + grow] = v.y;
                    }
                } else {
                    float2 v = make_float2(cx, cy);
                    *(float2*)&g_inproj[(size_t)grow * RES + col] = v;
                }
            }
}

/* ================= transpose: dst[c][r] = src[r][c] ======================= */
__global__ void transpose_kernel(const float* __restrict__ src, int rows, int cols, int which)
{
    float* dst = which ? g_WinT : g_WresT;
    __shared__ float t[32][33];
    int c0 = blockIdx.x * 32, r0 = blockIdx.y * 32;
    for (int j = threadIdx.y; j < 32; j += 8)
        t[j][threadIdx.x] = src[(size_t)(r0 + j) * cols + c0 + threadIdx.x];
    __syncthreads();
    for (int j = threadIdx.y; j < 32; j += 8)
        dst[(size_t)(c0 + j) * rows + r0 + threadIdx.x] = t[threadIdx.x][j];
}

/* ====== transpose Cholesky factors: g_LT[b][j][i] = g_A[b][i][j] ========== */
__global__ void transL_kernel()
{
    const int b = blockIdx.z;
    const float* src = g_A + (size_t)b * TLEN * TLEN;
    float* dst = g_LT + (size_t)b * TLEN * TLEN;
    __shared__ float t[32][33];
    int c0 = blockIdx.x * 32, r0 = blockIdx.y * 32;
    for (int j = threadIdx.y; j < 32; j += 8)
        t[j][threadIdx.x] = src[(size_t)(r0 + j) * TLEN + c0 + threadIdx.x];
    __syncthreads();
    for (int j = threadIdx.y; j < 32; j += 8)
        dst[(size_t)(c0 + j) * TLEN + r0 + threadIdx.x] = t[threadIdx.x][j];
}

/* =================== step s=0 (state was zero) ============================ */
__global__ __launch_bounds__(256) void init0_kernel()
{
    int idx = blockIdx.x * 256 + threadIdx.x;
    int row = idx >> 11, qq = idx & 2047;
    int b = row >> 7, w = row & 127;
    int t = 4 * w - 2;
    float v = 0.f;
    if (t >= 0) v = 0.3f * sinf(g_inproj[((size_t)(b << 9) + t) * RES + qq]);
    g_S0[idx] = v;
}

/* ============ blocked Cholesky, NB=64 ===================================== */
__global__ __launch_bounds__(256) void chol_panel_kernel(int p)
{
    const int b = blockIdx.x;
    float* Ab = g_A + (size_t)b * TLEN * TLEN;
    const int jb = p * 64;
    __shared__ float L11[64][65];
    const int tid = threadIdx.x;
    for (int idx = tid; idx < 64 * 64; idx += 256) {
        int r = idx >> 6, c = idx & 63;
        L11[r][c] = Ab[(jb + r) * TLEN + jb + c];
    }
    __syncthreads();
    for (int k = 0; k < 64; k++) {
        if (tid == 0) L11[k][k] = sqrtf(L11[k][k]);
        __syncthreads();
        if (tid > k && tid < 64) L11[tid][k] /= L11[k][k];
        __syncthreads();
        for (int idx = tid; idx < 64 * 64; idx += 256) {
            int r = idx >> 6, c = idx & 63;
            if (r > k && c > k && c <= r) L11[r][c] -= L11[r][k] * L11[c][k];
        }
        __syncthreads();
    }
    for (int idx = tid; idx < 64 * 64; idx += 256) {
        int r = idx >> 6, c = idx & 63;
        if (c <= r) Ab[(jb + r) * TLEN + jb + c] = L11[r][c];
    }
    __syncthreads();
    const int m = TLEN - jb - 64;
    for (int r = tid; r < m; r += 256) {
        int i = jb + 64 + r;
        float a[64];
        #pragma unroll
        for (int c = 0; c < 64; c++) a[c] = Ab[i * TLEN + jb + c];
        #pragma unroll
        for (int k = 0; k < 64; k++) {
            float sv = a[k];
            #pragma unroll
            for (int q = 0; q < k; q++) sv -= a[q] * L11[k][q];
            a[k] = sv / L11[k][k];
        }
        #pragma unroll
        for (int c = 0; c < 64; c++) Ab[i * TLEN + jb + c] = a[c];
    }
}

__global__ __launch_bounds__(256) void chol_update_kernel(int p)
{
    const int jb = p * 64 + 64;
    int idx = blockIdx.x;
    int ti = 0;
    while ((ti + 1) * (ti + 2) / 2 <= idx) ti++;
    int tj = idx - ti * (ti + 1) / 2;
    const int b = blockIdx.y;
    float* Ab = g_A + (size_t)b * TLEN * TLEN;
    const int r0 = jb + ti * 64, c0 = jb + tj * 64;
    __shared__ float La[64][65], Lb[64][65];
    const int tid = threadIdx.x;
    for (int q = tid; q < 64 * 64; q += 256) {
        int r = q >> 6, c = q & 63;
        La[r][c] = Ab[(r0 + r) * TLEN + p * 64 + c];
        Lb[r][c] = Ab[(c0 + r) * TLEN + p * 64 + c];
    }
    __syncthreads();
    const int tx = tid & 15, ty = tid >> 4;
    float acc[4][4] = {};
    #pragma unroll
    for (int k = 0; k < 64; k++) {
        float ar[4], bc[4];
        #pragma unroll
        for (int i = 0; i < 4; i++) ar[i] = La[ty * 4 + i][k];
        #pragma unroll
        for (int j = 0; j < 4; j++) bc[j] = Lb[tx * 4 + j][k];
        #pragma unroll
        for (int i = 0; i < 4; i++)
            #pragma unroll
            for (int j = 0; j < 4; j++)
                acc[i][j] += ar[i] * bc[j];
    }
    #pragma unroll
    for (int i = 0; i < 4; i++)
        #pragma unroll
        for (int j = 0; j < 4; j++)
            Ab[(r0 + ty * 4 + i) * TLEN + c0 + tx * 4 + j] -= acc[i][j];
}

/* ============ triangular solves, 64 RHS in registers ====================== */
__global__ __launch_bounds__(512) void solve_kernel(const float* __restrict__ Y)
{
    const int b = blockIdx.x;
    const int i = threadIdx.x;
    const float* __restrict__ Ab = g_A + (size_t)b * TLEN * TLEN;
    const float* __restrict__ Lt = g_LT + (size_t)b * TLEN * TLEN;
    float acc[OUTD];
    #pragma unroll
    for (int o = 0; o < OUTD; o++) acc[o] = Y[((size_t)b * TLEN + i) * OUTD + o];
    __shared__ float zrow[OUTD];
    /* forward: L w = y   (coalesced via LT: LT[j][i] = L[i][j]) */
    for (int j = 0; j < TLEN; j++) {
        if (i == j) {
            float dinv = 1.f / Ab[j * TLEN + j];
            #pragma unroll
            for (int o = 0; o < OUTD; o++) { acc[o] *= dinv; zrow[o] = acc[o]; }
        }
        __syncthreads();
        if (i > j) {
            float lij = Lt[j * TLEN + i];
            #pragma unroll
            for (int o = 0; o < OUTD; o++) acc[o] -= lij * zrow[o];
        }
        __syncthreads();
    }
    /* backward: L^T z = w   (row j of L, coalesced) */
    for (int j = TLEN - 1; j >= 0; j--) {
        if (i == j) {
            float dinv = 1.f / Ab[j * TLEN + j];
            #pragma unroll
            for (int o = 0; o < OUTD; o++) { acc[o] *= dinv; zrow[o] = acc[o]; }
        }
        __syncthreads();
        if (i < j) {
            float lji = Ab[j * TLEN + i];
            #pragma unroll
            for (int o = 0; o < OUTD; o++) acc[o] -= lji * zrow[o];
        }
        __syncthreads();
    }
    #pragma unroll
    for (int o = 0; o < OUTD; o++) g_Z[((size_t)b * TLEN + i) * OUTD + o] = acc[o];
}

/* ============ W = Xb^T Z  (2048 x 64, K=512) ============================== */
__global__ __launch_bounds__(256) void wout_kernel(float* __restrict__ out)
{
    const int b = blockIdx.y;
    const float* __restrict__ X = g_rs + (size_t)b * TLEN * RES;
    const float* __restrict__ Zb = g_Z + (size_t)b * TLEN * OUTD;
    const int d0 = blockIdx.x * 128;
    __shared__ float As2[16][132];
    __shared__ float Bs2[16][68];
    const int tid = threadIdx.x;
    const int lr = tid >> 4, lc = (tid & 15) * 4;
    const int ty = tid >> 4, tx = tid & 15;
    float acc[8][4] = {};
    for (int k0 = 0; k0 < TLEN; k0 += 16) {
        *(float4*)&As2[lr][lc]      = *(const float4*)&X[(size_t)(k0 + lr) * RES + d0 + lc];
        *(float4*)&As2[lr][lc + 64] = *(const float4*)&X[(size_t)(k0 + lr) * RES + d0 + lc + 64];
        *(float4*)&Bs2[lr][lc]      = *(const float4*)&Zb[(k0 + lr) * OUTD + lc];
        __syncthreads();
        #pragma unroll
        for (int k = 0; k < 16; k++) {
            float fa[8], fb[4];
            *(float4*)&fa[0] = *(const float4*)&As2[k][ty * 8];
            *(float4*)&fa[4] = *(const float4*)&As2[k][ty * 8 + 4];
            *(float4*)&fb[0] = *(const float4*)&Bs2[k][tx * 4];
            #pragma unroll
            for (int i = 0; i < 8; i++)
                #pragma unroll
                for (int j = 0; j < 4; j++)
                    acc[i][j] += fa[i] * fb[j];
        }
        __syncthreads();
    }
    #pragma unroll
    for (int i = 0; i < 8; i++)
        #pragma unroll
        for (int j = 0; j < 4; j++)
            out[((size_t)b * RES + d0 + ty * 8 + i) * OUTD + tx * 4 + j] = acc[i][j];
}

__global__ void bias_kernel(float* __restrict__ out)
{
    const int b = blockIdx.x, o = threadIdx.x;
    float s = 0.f;
    for (int n = 0; n < TLEN; n++) s += g_Z[((size_t)b * TLEN + n) * OUTD + o];
    out[(size_t)BATCH * RES * OUTD + b * OUTD + o] = s;
}

/* ======================= launch ======================= */
extern "C" void kernel_launch(void* const* d_in, const int* in_sizes, int n_in,
                              void* d_out, int out_size)
{
    const float* input  = (const float*)d_in[0];
    const float* target = (const float*)d_in[1];
    const float* W_res  = (const float*)d_in[2];
    const float* W_in   = (const float*)d_in[3];
    const float* lam    = (const float*)d_in[4];
    float* out = (float*)d_out;

    cudaFuncSetAttribute(tc_kernel, cudaFuncAttributeMaxDynamicSharedMemorySize, SMEM_DYN);

    /* transposes for K-major A·B^T form */
    transpose_kernel<<<dim3(RES / 32, RES / 32), dim3(32, 8)>>>(W_res, RES, RES, 0);
    transpose_kernel<<<dim3(RES / 32, INDIM / 32), dim3(32, 8)>>>(W_in, INDIM, RES, 1);

    /* 1. input projection (tensor) */
    tc_kernel<<<dim3(RES / 128, NROWS / 128), 512, SMEM_DYN>>>(2, input, 0, 0, nullptr);

    /* 2. reservoir */
    init0_kernel<<<(MROWS * RES) / 256, 256>>>();
    int flip = 0;
    for (int s = 1; s <= 5; s++) {
        tc_kernel<<<dim3(RES / 128, MROWS / 128), 512, SMEM_DYN>>>(0, nullptr, s, flip, nullptr);
        flip ^= 1;
    }

    /* 3. gram (tensor, symmetric: 10 lower tiles) */
    tc_kernel<<<dim3(10, 1, BATCH), 512, SMEM_DYN>>>(1, nullptr, 0, 0, lam);

    /* 4. batched blocked Cholesky */
    for (int p = 0; p < 8; p++) {
        chol_panel_kernel<<<BATCH, 256>>>(p);
        if (p < 7) {
            int mt = 7 - p;
            chol_update_kernel<<<dim3(mt * (mt + 1) / 2, BATCH), 256>>>(p);
        }
    }

    /* 4b. transpose L for coalesced forward solve */
    transL_kernel<<<dim3(16, 16, BATCH), dim3(32, 8)>>>();

    /* 5. triangular solves */
    solve_kernel<<<BATCH, 512>>>(target);

    /* 6. readout */
    wout_kernel<<<dim3(RES / 128, BATCH), 256>>>(out);
    bias_kernel<<<BATCH, 64>>>(out);

    (void)in_sizes; (void)n_in; (void)out_size;
}

// round 6
// speedup vs baseline: 1.6245x; 1.3933x over previous
#include <cuda_runtime.h>
#include <cuda_fp16.h>
#include <math.h>
#include <stdint.h>

#define BATCH 32
#define TLEN  512
#define INDIM 128
#define RES   2048
#define OUTD  64
#define NWIN  128
#define MROWS (BATCH*NWIN)   /* 4096  reservoir rows (b,w) */
#define NROWS (BATCH*TLEN)   /* 16384 time rows (b,t)      */

/* ---------------- scratch (device globals; no allocations) ---------------- */
__device__ float g_inproj[NROWS * RES];    /* input @ W_in (fp32)   128 MB */
__device__ float g_S0[MROWS * RES];        /* state ping (fp32)      32 MB */
__device__ float g_S1[MROWS * RES];        /* state pong (fp32)      32 MB */
__device__ float g_rs[NROWS * RES];        /* reservoir states      128 MB */
__device__ float g_A[BATCH * TLEN * TLEN]; /* gram matrices          32 MB */
__device__ float g_LT[BATCH * TLEN * TLEN];/* L transposed           32 MB */
__device__ float g_Z[BATCH * TLEN * OUTD]; /* solve result            4 MB */
/* fp16 split planes */
__device__ half g_Shi0[MROWS * RES], g_Slo0[MROWS * RES];   /* 16MB each */
__device__ half g_Shi1[MROWS * RES], g_Slo1[MROWS * RES];
__device__ half g_rshi[NROWS * RES], g_rslo[NROWS * RES];   /* 64MB each */
__device__ half g_Whi[RES * RES],   g_Wlo[RES * RES];       /* WresT     */
__device__ half g_WinHi[RES * INDIM], g_WinLo[RES * INDIM]; /* WinT      */
__device__ half g_xhi[NROWS * INDIM], g_xlo[NROWS * INDIM]; /* input     */

/* ====================== helpers ====================== */
__device__ __forceinline__ uint32_t smem_u32(const void* p) {
    uint32_t a;
    asm("{ .reg .u64 t; cvta.to.shared.u64 t, %1; cvt.u32.u64 %0, t; }" : "=r"(a) : "l"(p));
    return a;
}
__device__ __forceinline__ void cpasync16(uint32_t dst, const void* src) {
    asm volatile("cp.async.cg.shared.global [%0], [%1], 16;" :: "r"(dst), "l"(src));
}
__device__ __forceinline__ void cp_commit() { asm volatile("cp.async.commit_group;" ::: "memory"); }
__device__ __forceinline__ void cp_wait1()  { asm volatile("cp.async.wait_group 1;" ::: "memory"); }
__device__ __forceinline__ void cp_wait0()  { asm volatile("cp.async.wait_group 0;" ::: "memory"); }

__device__ __forceinline__ void ldsm4(uint32_t* r, uint32_t addr) {
    asm volatile("ldmatrix.sync.aligned.m8n8.x4.shared.b16 {%0,%1,%2,%3}, [%4];"
        : "=r"(r[0]), "=r"(r[1]), "=r"(r[2]), "=r"(r[3]) : "r"(addr));
}
__device__ __forceinline__ void mma16816(float* d, const uint32_t* a, uint32_t b0, uint32_t b1) {
    asm volatile(
        "mma.sync.aligned.m16n8k16.row.col.f32.f16.f16.f32 "
        "{%0,%1,%2,%3},{%4,%5,%6,%7},{%8,%9},{%0,%1,%2,%3};"
        : "+f"(d[0]), "+f"(d[1]), "+f"(d[2]), "+f"(d[3])
        : "r"(a[0]), "r"(a[1]), "r"(a[2]), "r"(a[3]), "r"(b0), "r"(b1));
}
__device__ __forceinline__ void split16(float f, half& h, half& l) {
    h = __float2half_rn(f);
    l = __float2half_rn(f - __half2float(h));
}

/* ============ fp16x3 GEMM kernel (mma.sync m16n8k16) ======================
   C[row0+i][col0+j] = sum_k A[i][k]*B[j][k]  from pre-split hi/lo planes.
   mode 0: reservoir step (epilogue: leaky-sin, writes Snew fp32+planes, rs)
   mode 1: gram lower tiles (+1, +reg*I on diag)
   mode 2: inproj (plain fp32 store)
   SMEM: 2 stages x 4 planes(Ahi,Alo,Bhi,Blo) x [128 rows][32 halves=64B],
   16B-seg XOR swizzle: seg' = seg ^ ((row>>1)&3)  -> LDSM conflict-free.  */
#define PLANE_B 8192
#define STAGE_B (4*PLANE_B)
#define SMEM_DYN (2*STAGE_B)   /* 65536 */

__global__ __launch_bounds__(512, 1) void tc_kernel(
    int mode, int s, int flip, const float* __restrict__ lam)
{
    extern __shared__ char smem[];
    const uint32_t smem_u = smem_u32(smem);

    const int tid = threadIdx.x;
    const int wid = tid >> 5, lane = tid & 31;
    const int gid = lane >> 2, tig = lane & 3;
    const int m = lane >> 3, l7 = lane & 7;
    const int warpM = wid >> 2, warpN = wid & 3;
    const int rowBase = warpM * 32, colBase = warpN * 32;

    int row0, col0, gti = 0, gtj = 0;
    if (mode == 1) {
        int x = blockIdx.x, ti = 0;
        while ((ti + 1) * (ti + 2) / 2 <= x) ti++;
        gti = ti; gtj = x - ti * (ti + 1) / 2;
        row0 = gti * 128; col0 = gtj * 128;
    } else {
        row0 = blockIdx.y * 128; col0 = blockIdx.x * 128;
    }

    const half *Ahi, *Alo, *Bhi, *Blo; int K;
    if (mode == 0) {
        Ahi = flip ? g_Shi1 : g_Shi0; Alo = flip ? g_Slo1 : g_Slo0;
        Bhi = g_Whi; Blo = g_Wlo; K = RES;
    } else if (mode == 1) {
        size_t base = (size_t)blockIdx.z * TLEN * RES;
        Ahi = g_rshi + base; Alo = g_rslo + base;
        Bhi = Ahi; Blo = Alo; K = RES;
    } else {
        Ahi = g_xhi; Alo = g_xlo; Bhi = g_WinHi; Blo = g_WinLo; K = INDIM;
    }
    const int nIter = K >> 5;

    float acc[2][4][4] = {};

    /* per-lane LDSM address components */
    uint32_t aRow64[2], aSwz[2], bRow64[2], bSwz[2];
    #pragma unroll
    for (int mt = 0; mt < 2; mt++) {
        uint32_t r = rowBase + mt * 16 + (m & 1) * 8 + l7;
        aRow64[mt] = r * 64; aSwz[mt] = (r >> 1) & 3;
    }
    #pragma unroll
    for (int np = 0; np < 2; np++) {
        uint32_t n = colBase + (np * 2 + (m >> 1)) * 8 + l7;
        bRow64[np] = n * 64; bSwz[np] = (n >> 1) & 3;
    }
    const uint32_t amk = (uint32_t)(m >> 1);   /* A k-subblock from matrix id */
    const uint32_t bmk = (uint32_t)(m & 1);    /* B k-subblock from matrix id */

    /* ---- loader: 2048 16B segments per 32-k chunk ---- */
    auto load_chunk = [&](int it, int buf) {
        const int k0 = it << 5;
        const uint32_t sb = smem_u + buf * STAGE_B;
        #pragma unroll
        for (int q = 0; q < 4; q++) {
            int idx = tid + q * 512;
            int c = idx & 3, r = (idx >> 2) & 127, p = (idx >> 9) & 1, op = idx >> 10;
            const half* gp = op ? (p ? Blo : Bhi) : (p ? Alo : Ahi);
            int rowg = (op ? col0 : row0) + r;
            const half* src = gp + (size_t)rowg * K + k0 + c * 8;
            uint32_t dst = sb + (uint32_t)(op * 2 + p) * PLANE_B
                         + (uint32_t)r * 64 + (uint32_t)((c ^ ((r >> 1) & 3)) * 16);
            cpasync16(dst, src);
        }
    };

    load_chunk(0, 0);
    cp_commit();

    for (int it = 0; it < nIter; ++it) {
        const int buf = it & 1;
        if (it + 1 < nIter) { load_chunk(it + 1, buf ^ 1); cp_commit(); cp_wait1(); }
        else                { cp_wait0(); }
        __syncthreads();

        const uint32_t sb = smem_u + buf * STAGE_B;
        const uint32_t pAh = sb, pAl = sb + PLANE_B, pBh = sb + 2 * PLANE_B, pBl = sb + 3 * PLANE_B;
        #pragma unroll
        for (int h16 = 0; h16 < 2; h16++) {
            uint32_t ah[2][4], al[2][4], bh[2][4], bl[2][4];
            #pragma unroll
            for (int mt = 0; mt < 2; mt++) {
                uint32_t off = aRow64[mt] + (((h16 * 2 + amk) ^ aSwz[mt]) * 16);
                ldsm4(ah[mt], pAh + off);
                ldsm4(al[mt], pAl + off);
            }
            #pragma unroll
            for (int np = 0; np < 2; np++) {
                uint32_t off = bRow64[np] + (((h16 * 2 + bmk) ^ bSwz[np]) * 16);
                ldsm4(bh[np], pBh + off);
                ldsm4(bl[np], pBl + off);
            }
            #pragma unroll
            for (int mt = 0; mt < 2; mt++)
                #pragma unroll
                for (int nt = 0; nt < 4; nt++) {
                    uint32_t b0h = bh[nt >> 1][(nt & 1) * 2], b1h = bh[nt >> 1][(nt & 1) * 2 + 1];
                    uint32_t b0l = bl[nt >> 1][(nt & 1) * 2], b1l = bl[nt >> 1][(nt & 1) * 2 + 1];
                    mma16816(acc[mt][nt], ah[mt], b0h, b1h);
                    mma16816(acc[mt][nt], ah[mt], b0l, b1l);
                    mma16816(acc[mt][nt], al[mt], b0h, b1h);
                }
        }
        __syncthreads();
    }

    /* -------------------- epilogue (register -> global) -------------------- */
    float regc = 0.f;
    if (mode == 1) { float l = lam[0]; regc = log1pf(expf(l)); }
    const float* Sold = flip ? g_S1 : g_S0;
    float* Snew = flip ? g_S0 : g_S1;
    half* ShiN = flip ? g_Shi0 : g_Shi1;
    half* SloN = flip ? g_Slo0 : g_Slo1;

    #pragma unroll
    for (int mt = 0; mt < 2; mt++)
        #pragma unroll
        for (int nt = 0; nt < 4; nt++)
            #pragma unroll
            for (int h = 0; h < 2; h++) {
                int grow = row0 + rowBase + mt * 16 + gid + h * 8;
                int col = col0 + colBase + nt * 8 + tig * 2;
                float cx = acc[mt][nt][h * 2 + 0];
                float cy = acc[mt][nt][h * 2 + 1];
                if (mode == 0) {
                    int b = grow >> 7, w = grow & 127;
                    int t = 4 * w + s - 2;
                    float2 so = *(const float2*)&Sold[(size_t)grow * RES + col];
                    float2 u = make_float2(0.f, 0.f);
                    if (t >= 0) u = *(const float2*)&g_inproj[((size_t)(b << 9) + t) * RES + col];
                    float2 v;
                    v.x = 0.7f * so.x + 0.3f * sinf(cx + u.x);
                    v.y = 0.7f * so.y + 0.3f * sinf(cy + u.y);
                    *(float2*)&Snew[(size_t)grow * RES + col] = v;
                    half hx, lx, hy, ly;
                    split16(v.x, hx, lx); split16(v.y, hy, ly);
                    *(half2*)&ShiN[(size_t)grow * RES + col] = __halves2half2(hx, hy);
                    *(half2*)&SloN[(size_t)grow * RES + col] = __halves2half2(lx, ly);
                    if (s >= 2) {
                        size_t ro = ((size_t)(b << 9) + t) * RES + col;
                        *(float2*)&g_rs[ro] = v;
                        *(half2*)&g_rshi[ro] = __halves2half2(hx, hy);
                        *(half2*)&g_rslo[ro] = __halves2half2(lx, ly);
                    }
                } else if (mode == 1) {
                    float* Abm = g_A + (size_t)blockIdx.z * TLEN * TLEN;
                    float2 v;
                    v.x = cx + 1.0f + ((grow == col + 0) ? regc : 0.f);
                    v.y = cy + 1.0f + ((grow == col + 1) ? regc : 0.f);
                    *(float2*)&Abm[(size_t)grow * TLEN + col] = v;
                } else {
                    *(float2*)&g_inproj[(size_t)grow * RES + col] = make_float2(cx, cy);
                }
            }
}

/* ============ split+transpose weights: dst[c][r] = split(src[r][c]) ======= */
__global__ void split_trans_kernel(const float* __restrict__ src, int rows, int cols, int which)
{
    half* dh = which ? g_WinHi : g_Whi;
    half* dl = which ? g_WinLo : g_Wlo;
    __shared__ float t[32][33];
    int c0 = blockIdx.x * 32, r0 = blockIdx.y * 32;
    for (int j = threadIdx.y; j < 32; j += 8)
        t[j][threadIdx.x] = src[(size_t)(r0 + j) * cols + c0 + threadIdx.x];
    __syncthreads();
    for (int j = threadIdx.y; j < 32; j += 8) {
        float f = t[threadIdx.x][j];
        half h, l; split16(f, h, l);
        size_t o = (size_t)(c0 + j) * rows + r0 + threadIdx.x;
        dh[o] = h; dl[o] = l;
    }
}

/* ============ split input rows (no transpose) ============================= */
__global__ void split_input_kernel(const float* __restrict__ src)
{
    int idx = blockIdx.x * 256 + threadIdx.x;   /* NROWS*INDIM */
    float f = src[idx];
    half h, l; split16(f, h, l);
    g_xhi[idx] = h; g_xlo[idx] = l;
}

/* =================== step s=0 (state was zero) ============================ */
__global__ __launch_bounds__(256) void init0_kernel()
{
    int idx = blockIdx.x * 256 + threadIdx.x;   /* MROWS*RES */
    int row = idx >> 11, qq = idx & 2047;
    int b = row >> 7, w = row & 127;
    int t = 4 * w - 2;
    float v = 0.f;
    if (t >= 0) v = 0.3f * sinf(g_inproj[((size_t)(b << 9) + t) * RES + qq]);
    g_S0[idx] = v;
    half h, l; split16(v, h, l);
    g_Shi0[idx] = h; g_Slo0[idx] = l;
}

/* ============ mirror upper 128-blocks of gram from lower ================== */
__global__ void mirror_kernel()
{
    int r0 = blockIdx.y * 32, c0 = blockIdx.x * 32;
    if ((r0 >> 7) >= (c0 >> 7)) return;        /* only strictly-upper blocks */
    float* Ab = g_A + (size_t)blockIdx.z * TLEN * TLEN;
    __shared__ float t[32][33];
    for (int j = threadIdx.y; j < 32; j += 8)
        t[j][threadIdx.x] = Ab[(size_t)(c0 + j) * TLEN + r0 + threadIdx.x];
    __syncthreads();
    for (int j = threadIdx.y; j < 32; j += 8)
        Ab[(size_t)(r0 + j) * TLEN + c0 + threadIdx.x] = t[threadIdx.x][j];
}

/* ====== transpose Cholesky factors: g_LT[b][j][i] = g_A[b][i][j] ========== */
__global__ void transL_kernel()
{
    const int b = blockIdx.z;
    const float* src = g_A + (size_t)b * TLEN * TLEN;
    float* dst = g_LT + (size_t)b * TLEN * TLEN;
    __shared__ float t[32][33];
    int c0 = blockIdx.x * 32, r0 = blockIdx.y * 32;
    for (int j = threadIdx.y; j < 32; j += 8)
        t[j][threadIdx.x] = src[(size_t)(r0 + j) * TLEN + c0 + threadIdx.x];
    __syncthreads();
    for (int j = threadIdx.y; j < 32; j += 8)
        dst[(size_t)(c0 + j) * TLEN + r0 + threadIdx.x] = t[threadIdx.x][j];
}

/* ============ blocked Cholesky, NB=64 ===================================== */
__global__ __launch_bounds__(256) void chol_panel_kernel(int p)
{
    const int b = blockIdx.x;
    float* Ab = g_A + (size_t)b * TLEN * TLEN;
    const int jb = p * 64;
    __shared__ float L11[64][65];
    const int tid = threadIdx.x;
    for (int idx = tid; idx < 64 * 64; idx += 256) {
        int r = idx >> 6, c = idx & 63;
        L11[r][c] = Ab[(jb + r) * TLEN + jb + c];
    }
    __syncthreads();
    for (int k = 0; k < 64; k++) {
        if (tid == 0) L11[k][k] = sqrtf(L11[k][k]);
        __syncthreads();
        if (tid > k && tid < 64) L11[tid][k] /= L11[k][k];
        __syncthreads();
        for (int idx = tid; idx < 64 * 64; idx += 256) {
            int r = idx >> 6, c = idx & 63;
            if (r > k && c > k && c <= r) L11[r][c] -= L11[r][k] * L11[c][k];
        }
        __syncthreads();
    }
    for (int idx = tid; idx < 64 * 64; idx += 256) {
        int r = idx >> 6, c = idx & 63;
        if (c <= r) Ab[(jb + r) * TLEN + jb + c] = L11[r][c];
    }
    __syncthreads();
    const int mrows = TLEN - jb - 64;
    for (int r = tid; r < mrows; r += 256) {
        int i = jb + 64 + r;
        float a[64];
        #pragma unroll
        for (int c = 0; c < 64; c++) a[c] = Ab[i * TLEN + jb + c];
        #pragma unroll
        for (int k = 0; k < 64; k++) {
            float sv = a[k];
            #pragma unroll
            for (int q = 0; q < k; q++) sv -= a[q] * L11[k][q];
            a[k] = sv / L11[k][k];
        }
        #pragma unroll
        for (int c = 0; c < 64; c++) Ab[i * TLEN + jb + c] = a[c];
    }
}

__global__ __launch_bounds__(256) void chol_update_kernel(int p)
{
    const int jb = p * 64 + 64;
    int idx = blockIdx.x;
    int ti = 0;
    while ((ti + 1) * (ti + 2) / 2 <= idx) ti++;
    int tj = idx - ti * (ti + 1) / 2;
    const int b = blockIdx.y;
    float* Ab = g_A + (size_t)b * TLEN * TLEN;
    const int r0 = jb + ti * 64, c0 = jb + tj * 64;
    __shared__ float La[64][65], Lb[64][65];
    const int tid = threadIdx.x;
    for (int q = tid; q < 64 * 64; q += 256) {
        int r = q >> 6, c = q & 63;
        La[r][c] = Ab[(r0 + r) * TLEN + p * 64 + c];
        Lb[r][c] = Ab[(c0 + r) * TLEN + p * 64 + c];
    }
    __syncthreads();
    const int tx = tid & 15, ty = tid >> 4;
    float acc[4][4] = {};
    #pragma unroll
    for (int k = 0; k < 64; k++) {
        float ar[4], bc[4];
        #pragma unroll
        for (int i = 0; i < 4; i++) ar[i] = La[ty * 4 + i][k];
        #pragma unroll
        for (int j = 0; j < 4; j++) bc[j] = Lb[tx * 4 + j][k];
        #pragma unroll
        for (int i = 0; i < 4; i++)
            #pragma unroll
            for (int j = 0; j < 4; j++)
                acc[i][j] += ar[i] * bc[j];
    }
    #pragma unroll
    for (int i = 0; i < 4; i++)
        #pragma unroll
        for (int j = 0; j < 4; j++)
            Ab[(r0 + ty * 4 + i) * TLEN + c0 + tx * 4 + j] -= acc[i][j];
}

/* ============ triangular solves, 64 RHS in registers ====================== */
__global__ __launch_bounds__(512) void solve_kernel(const float* __restrict__ Y)
{
    const int b = blockIdx.x;
    const int i = threadIdx.x;
    const float* __restrict__ Ab = g_A + (size_t)b * TLEN * TLEN;
    const float* __restrict__ Lt = g_LT + (size_t)b * TLEN * TLEN;
    float acc[OUTD];
    #pragma unroll
    for (int o = 0; o < OUTD; o++) acc[o] = Y[((size_t)b * TLEN + i) * OUTD + o];
    __shared__ float zrow[OUTD];
    for (int j = 0; j < TLEN; j++) {
        if (i == j) {
            float dinv = 1.f / Ab[j * TLEN + j];
            #pragma unroll
            for (int o = 0; o < OUTD; o++) { acc[o] *= dinv; zrow[o] = acc[o]; }
        }
        __syncthreads();
        if (i > j) {
            float lij = Lt[j * TLEN + i];
            #pragma unroll
            for (int o = 0; o < OUTD; o++) acc[o] -= lij * zrow[o];
        }
        __syncthreads();
    }
    for (int j = TLEN - 1; j >= 0; j--) {
        if (i == j) {
            float dinv = 1.f / Ab[j * TLEN + j];
            #pragma unroll
            for (int o = 0; o < OUTD; o++) { acc[o] *= dinv; zrow[o] = acc[o]; }
        }
        __syncthreads();
        if (i < j) {
            float lji = Ab[j * TLEN + i];
            #pragma unroll
            for (int o = 0; o < OUTD; o++) acc[o] -= lji * zrow[o];
        }
        __syncthreads();
    }
    #pragma unroll
    for (int o = 0; o < OUTD; o++) g_Z[((size_t)b * TLEN + i) * OUTD + o] = acc[o];
}

/* ============ W = Xb^T Z  (2048 x 64, K=512) ============================== */
__global__ __launch_bounds__(256) void wout_kernel(float* __restrict__ out)
{
    const int b = blockIdx.y;
    const float* __restrict__ X = g_rs + (size_t)b * TLEN * RES;
    const float* __restrict__ Zb = g_Z + (size_t)b * TLEN * OUTD;
    const int d0 = blockIdx.x * 128;
    __shared__ float As2[16][132];
    __shared__ float Bs2[16][68];
    const int tid = threadIdx.x;
    const int lr = tid >> 4, lc = (tid & 15) * 4;
    const int ty = tid >> 4, tx = tid & 15;
    float acc[8][4] = {};
    for (int k0 = 0; k0 < TLEN; k0 += 16) {
        *(float4*)&As2[lr][lc]      = *(const float4*)&X[(size_t)(k0 + lr) * RES + d0 + lc];
        *(float4*)&As2[lr][lc + 64] = *(const float4*)&X[(size_t)(k0 + lr) * RES + d0 + lc + 64];
        *(float4*)&Bs2[lr][lc]      = *(const float4*)&Zb[(k0 + lr) * OUTD + lc];
        __syncthreads();
        #pragma unroll
        for (int k = 0; k < 16; k++) {
            float fa[8], fb[4];
            *(float4*)&fa[0] = *(const float4*)&As2[k][ty * 8];
            *(float4*)&fa[4] = *(const float4*)&As2[k][ty * 8 + 4];
            *(float4*)&fb[0] = *(const float4*)&Bs2[k][tx * 4];
            #pragma unroll
            for (int i = 0; i < 8; i++)
                #pragma unroll
                for (int j = 0; j < 4; j++)
                    acc[i][j] += fa[i] * fb[j];
        }
        __syncthreads();
    }
    #pragma unroll
    for (int i = 0; i < 8; i++)
        #pragma unroll
        for (int j = 0; j < 4; j++)
            out[((size_t)b * RES + d0 + ty * 8 + i) * OUTD + tx * 4 + j] = acc[i][j];
}

__global__ void bias_kernel(float* __restrict__ out)
{
    const int b = blockIdx.x, o = threadIdx.x;
    float s = 0.f;
    for (int n = 0; n < TLEN; n++) s += g_Z[((size_t)b * TLEN + n) * OUTD + o];
    out[(size_t)BATCH * RES * OUTD + b * OUTD + o] = s;
}

/* ======================= launch ======================= */
extern "C" void kernel_launch(void* const* d_in, const int* in_sizes, int n_in,
                              void* d_out, int out_size)
{
    const float* input  = (const float*)d_in[0];
    const float* target = (const float*)d_in[1];
    const float* W_res  = (const float*)d_in[2];
    const float* W_in   = (const float*)d_in[3];
    const float* lam    = (const float*)d_in[4];
    float* out = (float*)d_out;

    cudaFuncSetAttribute(tc_kernel, cudaFuncAttributeMaxDynamicSharedMemorySize, SMEM_DYN);

    /* 0. split+transpose weights, split input */
    split_trans_kernel<<<dim3(RES / 32, RES / 32), dim3(32, 8)>>>(W_res, RES, RES, 0);
    split_trans_kernel<<<dim3(RES / 32, INDIM / 32), dim3(32, 8)>>>(W_in, INDIM, RES, 1);
    split_input_kernel<<<(NROWS * INDIM) / 256, 256>>>(input);

    /* 1. input projection */
    tc_kernel<<<dim3(RES / 128, NROWS / 128), 512, SMEM_DYN>>>(2, 0, 0, nullptr);

    /* 2. reservoir */
    init0_kernel<<<(MROWS * RES) / 256, 256>>>();
    int flip = 0;
    for (int s = 1; s <= 5; s++) {
        tc_kernel<<<dim3(RES / 128, MROWS / 128), 512, SMEM_DYN>>>(0, s, flip, nullptr);
        flip ^= 1;
    }

    /* 3. gram: 10 lower tiles + coalesced mirror */
    tc_kernel<<<dim3(10, 1, BATCH), 512, SMEM_DYN>>>(1, 0, 0, lam);
    mirror_kernel<<<dim3(16, 16, BATCH), dim3(32, 8)>>>();

    /* 4. batched blocked Cholesky */
    for (int p = 0; p < 8; p++) {
        chol_panel_kernel<<<BATCH, 256>>>(p);
        if (p < 7) {
            int mt = 7 - p;
            chol_update_kernel<<<dim3(mt * (mt + 1) / 2, BATCH), 256>>>(p);
        }
    }

    /* 4b. transpose L for coalesced forward solve */
    transL_kernel<<<dim3(16, 16, BATCH), dim3(32, 8)>>>();

    /* 5. triangular solves */
    solve_kernel<<<BATCH, 512>>>(target);

    /* 6. readout */
    wout_kernel<<<dim3(RES / 128, BATCH), 256>>>(out);
    bias_kernel<<<BATCH, 64>>>(out);

    (void)in_sizes; (void)n_in; (void)out_size;
}

// round 7
// speedup vs baseline: 1.7417x; 1.0722x over previous
#include <cuda_runtime.h>
#include <cuda_fp16.h>
#include <math.h>
#include <stdint.h>

#define BATCH 32
#define TLEN  512
#define INDIM 128
#define RES   2048
#define OUTD  64
#define NWIN  128
#define MROWS (BATCH*NWIN)   /* 4096  reservoir rows (b,w) */
#define NROWS (BATCH*TLEN)   /* 16384 time rows (b,t)      */

/* ---------------- scratch (device globals; no allocations) ---------------- */
__device__ float g_inproj[NROWS * RES];    /* input @ W_in (fp32)   128 MB */
__device__ float g_S0[MROWS * RES];        /* state ping (fp32)      32 MB */
__device__ float g_S1[MROWS * RES];        /* state pong (fp32)      32 MB */
__device__ float g_rs[NROWS * RES];        /* reservoir states      128 MB */
__device__ float g_A[BATCH * TLEN * TLEN]; /* gram matrices          32 MB */
__device__ float g_LT[BATCH * TLEN * TLEN];/* L transposed           32 MB */
__device__ float g_Z[BATCH * TLEN * OUTD]; /* solve result            4 MB */
/* fp16 split planes */
__device__ half g_Shi0[MROWS * RES], g_Slo0[MROWS * RES];
__device__ half g_Shi1[MROWS * RES], g_Slo1[MROWS * RES];
__device__ half g_rshi[NROWS * RES], g_rslo[NROWS * RES];
__device__ half g_Whi[RES * RES],   g_Wlo[RES * RES];       /* WresT     */
__device__ half g_WinHi[RES * INDIM], g_WinLo[RES * INDIM]; /* WinT      */
__device__ half g_xhi[NROWS * INDIM], g_xlo[NROWS * INDIM]; /* input     */

/* ====================== helpers ====================== */
__device__ __forceinline__ uint32_t smem_u32(const void* p) {
    uint32_t a;
    asm("{ .reg .u64 t; cvta.to.shared.u64 t, %1; cvt.u32.u64 %0, t; }" : "=r"(a) : "l"(p));
    return a;
}
__device__ __forceinline__ void cpasync16(uint32_t dst, const void* src) {
    asm volatile("cp.async.cg.shared.global [%0], [%1], 16;" :: "r"(dst), "l"(src));
}
__device__ __forceinline__ void cp_commit() { asm volatile("cp.async.commit_group;" ::: "memory"); }
__device__ __forceinline__ void cp_wait1()  { asm volatile("cp.async.wait_group 1;" ::: "memory"); }
__device__ __forceinline__ void cp_wait0()  { asm volatile("cp.async.wait_group 0;" ::: "memory"); }

__device__ __forceinline__ void ldsm4(uint32_t* r, uint32_t addr) {
    asm volatile("ldmatrix.sync.aligned.m8n8.x4.shared.b16 {%0,%1,%2,%3}, [%4];"
        : "=r"(r[0]), "=r"(r[1]), "=r"(r[2]), "=r"(r[3]) : "r"(addr));
}
__device__ __forceinline__ void mma16816(float* d, const uint32_t* a, uint32_t b0, uint32_t b1) {
    asm volatile(
        "mma.sync.aligned.m16n8k16.row.col.f32.f16.f16.f32 "
        "{%0,%1,%2,%3},{%4,%5,%6,%7},{%8,%9},{%0,%1,%2,%3};"
        : "+f"(d[0]), "+f"(d[1]), "+f"(d[2]), "+f"(d[3])
        : "r"(a[0]), "r"(a[1]), "r"(a[2]), "r"(a[3]), "r"(b0), "r"(b1));
}
__device__ __forceinline__ void split16(float f, half& h, half& l) {
    h = __float2half_rn(f);
    l = __float2half_rn(f - __half2float(h));
}

/* ============ fp16x3 GEMM kernel (mma.sync m16n8k16) ======================
   C[row0+i][col0+j] = sum_k A[i][k]*B[j][k]  from pre-split hi/lo planes.
   64-k chunks, 3 SMEM stages, ONE barrier per chunk.
   SMEM: 3 stages x 4 planes(Ahi,Alo,Bhi,Blo) x [128 rows][64 halves=128B],
   SW128 swizzle within each 128B row: seg' = seg ^ (row&7).               */
#define PLANE_B 16384
#define STAGE_B (4*PLANE_B)        /* 65536 */
#define SMEM_DYN (3*STAGE_B)       /* 196608 */

__global__ __launch_bounds__(512, 1) void tc_kernel(
    int mode, int s, int flip, const float* __restrict__ lam)
{
    extern __shared__ char smem[];
    const uint32_t smem_u = smem_u32(smem);

    const int tid = threadIdx.x;
    const int wid = tid >> 5, lane = tid & 31;
    const int gid = lane >> 2, tig = lane & 3;
    const int m = lane >> 3, l7 = lane & 7;
    const int warpM = wid >> 2, warpN = wid & 3;
    const int rowBase = warpM * 32, colBase = warpN * 32;

    int row0, col0, gti = 0, gtj = 0;
    if (mode == 1) {
        int x = blockIdx.x, ti = 0;
        while ((ti + 1) * (ti + 2) / 2 <= x) ti++;
        gti = ti; gtj = x - ti * (ti + 1) / 2;
        row0 = gti * 128; col0 = gtj * 128;
    } else {
        row0 = blockIdx.y * 128; col0 = blockIdx.x * 128;
    }

    const half *Ahi, *Alo, *Bhi, *Blo; int K;
    if (mode == 0) {
        Ahi = flip ? g_Shi1 : g_Shi0; Alo = flip ? g_Slo1 : g_Slo0;
        Bhi = g_Whi; Blo = g_Wlo; K = RES;
    } else if (mode == 1) {
        size_t base = (size_t)blockIdx.z * TLEN * RES;
        Ahi = g_rshi + base; Alo = g_rslo + base;
        Bhi = Ahi; Blo = Alo; K = RES;
    } else {
        Ahi = g_xhi; Alo = g_xlo; Bhi = g_WinHi; Blo = g_WinLo; K = INDIM;
    }
    const int nIter = K >> 6;   /* 64-k chunks */

    float acc[2][4][4] = {};

    /* per-lane LDSM address components: addr = plane + rowBytes + ((j ^ rx)*16) */
    uint32_t aRB[2], aX[2], bRB[2], bX[2];
    #pragma unroll
    for (int mt = 0; mt < 2; mt++) {
        uint32_t r = rowBase + mt * 16 + (m & 1) * 8 + l7;
        aRB[mt] = r * 128; aX[mt] = r & 7;
    }
    #pragma unroll
    for (int np = 0; np < 2; np++) {
        uint32_t n = colBase + (np * 2 + (m >> 1)) * 8 + l7;
        bRB[np] = n * 128; bX[np] = n & 7;
    }
    const uint32_t amk = (uint32_t)(m >> 1);   /* A k-subseg from matrix id */
    const uint32_t bmk = (uint32_t)(m & 1);    /* B k-subseg from matrix id */

    /* ---- loader: 4096 16B segments per 64-k chunk (8 per thread) ---- */
    auto load_chunk = [&](int it, int stage) {
        const int k0 = it << 6;
        const uint32_t sb = smem_u + (uint32_t)stage * STAGE_B;
        #pragma unroll
        for (int q = 0; q < 8; q++) {
            int idx = tid + q * 512;
            int c = idx & 7, r = (idx >> 3) & 127, p = (idx >> 10) & 1, op = idx >> 11;
            const half* gp = op ? (p ? Blo : Bhi) : (p ? Alo : Ahi);
            int rowg = (op ? col0 : row0) + r;
            const half* src = gp + (size_t)rowg * K + k0 + c * 8;
            uint32_t dst = sb + (uint32_t)(op * 2 + p) * PLANE_B
                         + (uint32_t)r * 128 + (uint32_t)((c ^ (r & 7)) * 16);
            cpasync16(dst, src);
        }
    };

    load_chunk(0, 0);
    cp_commit();
    if (nIter > 1) { load_chunk(1, 1); cp_commit(); }

    for (int it = 0; it < nIter; ++it) {
        if (it + 1 < nIter) cp_wait1(); else cp_wait0();
        __syncthreads();                 /* chunk it visible; stage (it+2)%3 reusable */
        if (it + 2 < nIter) { load_chunk(it + 2, (it + 2) % 3); cp_commit(); }

        const uint32_t sb = smem_u + (uint32_t)(it % 3) * STAGE_B;
        const uint32_t pAh = sb, pAl = sb + PLANE_B, pBh = sb + 2 * PLANE_B, pBl = sb + 3 * PLANE_B;
        #pragma unroll
        for (int h16 = 0; h16 < 4; h16++) {
            uint32_t ah[2][4], al[2][4], bh[2][4], bl[2][4];
            #pragma unroll
            for (int mt = 0; mt < 2; mt++) {
                uint32_t off = aRB[mt] + (((h16 * 2 + amk) ^ aX[mt]) * 16);
                ldsm4(ah[mt], pAh + off);
                ldsm4(al[mt], pAl + off);
            }
            #pragma unroll
            for (int np = 0; np < 2; np++) {
                uint32_t off = bRB[np] + (((h16 * 2 + bmk) ^ bX[np]) * 16);
                ldsm4(bh[np], pBh + off);
                ldsm4(bl[np], pBl + off);
            }
            #pragma unroll
            for (int mt = 0; mt < 2; mt++)
                #pragma unroll
                for (int nt = 0; nt < 4; nt++) {
                    uint32_t b0h = bh[nt >> 1][(nt & 1) * 2], b1h = bh[nt >> 1][(nt & 1) * 2 + 1];
                    uint32_t b0l = bl[nt >> 1][(nt & 1) * 2], b1l = bl[nt >> 1][(nt & 1) * 2 + 1];
                    mma16816(acc[mt][nt], ah[mt], b0h, b1h);
                    mma16816(acc[mt][nt], ah[mt], b0l, b1l);
                    mma16816(acc[mt][nt], al[mt], b0h, b1h);
                }
        }
    }

    /* -------------------- epilogue (register -> global) -------------------- */
    float regc = 0.f;
    if (mode == 1) { float l = lam[0]; regc = log1pf(expf(l)); }
    const float* Sold = flip ? g_S1 : g_S0;
    float* Snew = flip ? g_S0 : g_S1;
    half* ShiN = flip ? g_Shi0 : g_Shi1;
    half* SloN = flip ? g_Slo0 : g_Slo1;

    #pragma unroll
    for (int mt = 0; mt < 2; mt++)
        #pragma unroll
        for (int nt = 0; nt < 4; nt++)
            #pragma unroll
            for (int h = 0; h < 2; h++) {
                int grow = row0 + rowBase + mt * 16 + gid + h * 8;
                int col = col0 + colBase + nt * 8 + tig * 2;
                float cx = acc[mt][nt][h * 2 + 0];
                float cy = acc[mt][nt][h * 2 + 1];
                if (mode == 0) {
                    int b = grow >> 7, w = grow & 127;
                    int t = 4 * w + s - 2;
                    float2 so = *(const float2*)&Sold[(size_t)grow * RES + col];
                    float2 u = make_float2(0.f, 0.f);
                    if (t >= 0) u = *(const float2*)&g_inproj[((size_t)(b << 9) + t) * RES + col];
                    float2 v;
                    v.x = 0.7f * so.x + 0.3f * sinf(cx + u.x);
                    v.y = 0.7f * so.y + 0.3f * sinf(cy + u.y);
                    *(float2*)&Snew[(size_t)grow * RES + col] = v;
                    half hx, lx, hy, ly;
                    split16(v.x, hx, lx); split16(v.y, hy, ly);
                    *(half2*)&ShiN[(size_t)grow * RES + col] = __halves2half2(hx, hy);
                    *(half2*)&SloN[(size_t)grow * RES + col] = __halves2half2(lx, ly);
                    if (s >= 2) {
                        size_t ro = ((size_t)(b << 9) + t) * RES + col;
                        *(float2*)&g_rs[ro] = v;
                        *(half2*)&g_rshi[ro] = __halves2half2(hx, hy);
                        *(half2*)&g_rslo[ro] = __halves2half2(lx, ly);
                    }
                } else if (mode == 1) {
                    float* Abm = g_A + (size_t)blockIdx.z * TLEN * TLEN;
                    float2 v;
                    v.x = cx + 1.0f + ((grow == col + 0) ? regc : 0.f);
                    v.y = cy + 1.0f + ((grow == col + 1) ? regc : 0.f);
                    *(float2*)&Abm[(size_t)grow * TLEN + col] = v;
                } else {
                    *(float2*)&g_inproj[(size_t)grow * RES + col] = make_float2(cx, cy);
                }
            }
}

/* ============ split+transpose weights: dst[c][r] = split(src[r][c]) ======= */
__global__ void split_trans_kernel(const float* __restrict__ src, int rows, int cols, int which)
{
    half* dh = which ? g_WinHi : g_Whi;
    half* dl = which ? g_WinLo : g_Wlo;
    __shared__ float t[32][33];
    int c0 = blockIdx.x * 32, r0 = blockIdx.y * 32;
    for (int j = threadIdx.y; j < 32; j += 8)
        t[j][threadIdx.x] = src[(size_t)(r0 + j) * cols + c0 + threadIdx.x];
    __syncthreads();
    for (int j = threadIdx.y; j < 32; j += 8) {
        float f = t[threadIdx.x][j];
        half h, l; split16(f, h, l);
        size_t o = (size_t)(c0 + j) * rows + r0 + threadIdx.x;
        dh[o] = h; dl[o] = l;
    }
}

/* ============ split input rows (no transpose) ============================= */
__global__ void split_input_kernel(const float* __restrict__ src)
{
    int idx = blockIdx.x * 256 + threadIdx.x;
    float f = src[idx];
    half h, l; split16(f, h, l);
    g_xhi[idx] = h; g_xlo[idx] = l;
}

/* =================== step s=0 (state was zero) ============================ */
__global__ __launch_bounds__(256) void init0_kernel()
{
    int idx = blockIdx.x * 256 + threadIdx.x;
    int row = idx >> 11, qq = idx & 2047;
    int b = row >> 7, w = row & 127;
    int t = 4 * w - 2;
    float v = 0.f;
    if (t >= 0) v = 0.3f * sinf(g_inproj[((size_t)(b << 9) + t) * RES + qq]);
    g_S0[idx] = v;
    half h, l; split16(v, h, l);
    g_Shi0[idx] = h; g_Slo0[idx] = l;
}

/* ============ mirror upper 128-blocks of gram from lower ================== */
__global__ void mirror_kernel()
{
    int r0 = blockIdx.y * 32, c0 = blockIdx.x * 32;
    if ((r0 >> 7) >= (c0 >> 7)) return;
    float* Ab = g_A + (size_t)blockIdx.z * TLEN * TLEN;
    __shared__ float t[32][33];
    for (int j = threadIdx.y; j < 32; j += 8)
        t[j][threadIdx.x] = Ab[(size_t)(c0 + j) * TLEN + r0 + threadIdx.x];
    __syncthreads();
    for (int j = threadIdx.y; j < 32; j += 8)
        Ab[(size_t)(r0 + j) * TLEN + c0 + threadIdx.x] = t[threadIdx.x][j];
}

/* ====== transpose Cholesky factors: g_LT[b][j][i] = g_A[b][i][j] ========== */
__global__ void transL_kernel()
{
    const int b = blockIdx.z;
    const float* src = g_A + (size_t)b * TLEN * TLEN;
    float* dst = g_LT + (size_t)b * TLEN * TLEN;
    __shared__ float t[32][33];
    int c0 = blockIdx.x * 32, r0 = blockIdx.y * 32;
    for (int j = threadIdx.y; j < 32; j += 8)
        t[j][threadIdx.x] = src[(size_t)(r0 + j) * TLEN + c0 + threadIdx.x];
    __syncthreads();
    for (int j = threadIdx.y; j < 32; j += 8)
        dst[(size_t)(c0 + j) * TLEN + r0 + threadIdx.x] = t[threadIdx.x][j];
}

/* ============ blocked Cholesky, NB=64 ===================================== */
__global__ __launch_bounds__(256) void chol_panel_kernel(int p)
{
    const int b = blockIdx.x;
    float* Ab = g_A + (size_t)b * TLEN * TLEN;
    const int jb = p * 64;
    __shared__ float L11[64][65];
    const int tid = threadIdx.x;
    for (int idx = tid; idx < 64 * 64; idx += 256) {
        int r = idx >> 6, c = idx & 63;
        L11[r][c] = Ab[(jb + r) * TLEN + jb + c];
    }
    __syncthreads();
    for (int k = 0; k < 64; k++) {
        if (tid == 0) L11[k][k] = sqrtf(L11[k][k]);
        __syncthreads();
        if (tid > k && tid < 64) L11[tid][k] /= L11[k][k];
        __syncthreads();
        for (int idx = tid; idx < 64 * 64; idx += 256) {
            int r = idx >> 6, c = idx & 63;
            if (r > k && c > k && c <= r) L11[r][c] -= L11[r][k] * L11[c][k];
        }
        __syncthreads();
    }
    for (int idx = tid; idx < 64 * 64; idx += 256) {
        int r = idx >> 6, c = idx & 63;
        if (c <= r) Ab[(jb + r) * TLEN + jb + c] = L11[r][c];
    }
    __syncthreads();
    const int mrows = TLEN - jb - 64;
    for (int r = tid; r < mrows; r += 256) {
        int i = jb + 64 + r;
        float a[64];
        #pragma unroll
        for (int c = 0; c < 64; c++) a[c] = Ab[i * TLEN + jb + c];
        #pragma unroll
        for (int k = 0; k < 64; k++) {
            float sv = a[k];
            #pragma unroll
            for (int q = 0; q < k; q++) sv -= a[q] * L11[k][q];
            a[k] = sv / L11[k][k];
        }
        #pragma unroll
        for (int c = 0; c < 64; c++) Ab[i * TLEN + jb + c] = a[c];
    }
}

__global__ __launch_bounds__(256) void chol_update_kernel(int p)
{
    const int jb = p * 64 + 64;
    int idx = blockIdx.x;
    int ti = 0;
    while ((ti + 1) * (ti + 2) / 2 <= idx) ti++;
    int tj = idx - ti * (ti + 1) / 2;
    const int b = blockIdx.y;
    float* Ab = g_A + (size_t)b * TLEN * TLEN;
    const int r0 = jb + ti * 64, c0 = jb + tj * 64;
    __shared__ float La[64][65], Lb[64][65];
    const int tid = threadIdx.x;
    for (int q = tid; q < 64 * 64; q += 256) {
        int r = q >> 6, c = q & 63;
        La[r][c] = Ab[(r0 + r) * TLEN + p * 64 + c];
        Lb[r][c] = Ab[(c0 + r) * TLEN + p * 64 + c];
    }
    __syncthreads();
    const int tx = tid & 15, ty = tid >> 4;
    float acc[4][4] = {};
    #pragma unroll
    for (int k = 0; k < 64; k++) {
        float ar[4], bc[4];
        #pragma unroll
        for (int i = 0; i < 4; i++) ar[i] = La[ty * 4 + i][k];
        #pragma unroll
        for (int j = 0; j < 4; j++) bc[j] = Lb[tx * 4 + j][k];
        #pragma unroll
        for (int i = 0; i < 4; i++)
            #pragma unroll
            for (int j = 0; j < 4; j++)
                acc[i][j] += ar[i] * bc[j];
    }
    #pragma unroll
    for (int i = 0; i < 4; i++)
        #pragma unroll
        for (int j = 0; j < 4; j++)
            Ab[(r0 + ty * 4 + i) * TLEN + c0 + tx * 4 + j] -= acc[i][j];
}

/* ============ triangular solves, 64 RHS in registers ====================== */
__global__ __launch_bounds__(512) void solve_kernel(const float* __restrict__ Y)
{
    const int b = blockIdx.x;
    const int i = threadIdx.x;
    const float* __restrict__ Ab = g_A + (size_t)b * TLEN * TLEN;
    const float* __restrict__ Lt = g_LT + (size_t)b * TLEN * TLEN;
    float acc[OUTD];
    #pragma unroll
    for (int o = 0; o < OUTD; o++) acc[o] = Y[((size_t)b * TLEN + i) * OUTD + o];
    __shared__ float zrow[OUTD];
    for (int j = 0; j < TLEN; j++) {
        if (i == j) {
            float dinv = 1.f / Ab[j * TLEN + j];
            #pragma unroll
            for (int o = 0; o < OUTD; o++) { acc[o] *= dinv; zrow[o] = acc[o]; }
        }
        __syncthreads();
        if (i > j) {
            float lij = Lt[j * TLEN + i];
            #pragma unroll
            for (int o = 0; o < OUTD; o++) acc[o] -= lij * zrow[o];
        }
        __syncthreads();
    }
    for (int j = TLEN - 1; j >= 0; j--) {
        if (i == j) {
            float dinv = 1.f / Ab[j * TLEN + j];
            #pragma unroll
            for (int o = 0; o < OUTD; o++) { acc[o] *= dinv; zrow[o] = acc[o]; }
        }
        __syncthreads();
        if (i < j) {
            float lji = Ab[j * TLEN + i];
            #pragma unroll
            for (int o = 0; o < OUTD; o++) acc[o] -= lji * zrow[o];
        }
        __syncthreads();
    }
    #pragma unroll
    for (int o = 0; o < OUTD; o++) g_Z[((size_t)b * TLEN + i) * OUTD + o] = acc[o];
}

/* ============ W = Xb^T Z  (2048 x 64, K=512) ============================== */
__global__ __launch_bounds__(256) void wout_kernel(float* __restrict__ out)
{
    const int b = blockIdx.y;
    const float* __restrict__ X = g_rs + (size_t)b * TLEN * RES;
    const float* __restrict__ Zb = g_Z + (size_t)b * TLEN * OUTD;
    const int d0 = blockIdx.x * 128;
    __shared__ float As2[16][132];
    __shared__ float Bs2[16][68];
    const int tid = threadIdx.x;
    const int lr = tid >> 4, lc = (tid & 15) * 4;
    const int ty = tid >> 4, tx = tid & 15;
    float acc[8][4] = {};
    for (int k0 = 0; k0 < TLEN; k0 += 16) {
        *(float4*)&As2[lr][lc]      = *(const float4*)&X[(size_t)(k0 + lr) * RES + d0 + lc];
        *(float4*)&As2[lr][lc + 64] = *(const float4*)&X[(size_t)(k0 + lr) * RES + d0 + lc + 64];
        *(float4*)&Bs2[lr][lc]      = *(const float4*)&Zb[(k0 + lr) * OUTD + lc];
        __syncthreads();
        #pragma unroll
        for (int k = 0; k < 16; k++) {
            float fa[8], fb[4];
            *(float4*)&fa[0] = *(const float4*)&As2[k][ty * 8];
            *(float4*)&fa[4] = *(const float4*)&As2[k][ty * 8 + 4];
            *(float4*)&fb[0] = *(const float4*)&Bs2[k][tx * 4];
            #pragma unroll
            for (int i = 0; i < 8; i++)
                #pragma unroll
                for (int j = 0; j < 4; j++)
                    acc[i][j] += fa[i] * fb[j];
        }
        __syncthreads();
    }
    #pragma unroll
    for (int i = 0; i < 8; i++)
        #pragma unroll
        for (int j = 0; j < 4; j++)
            out[((size_t)b * RES + d0 + ty * 8 + i) * OUTD + tx * 4 + j] = acc[i][j];
}

__global__ void bias_kernel(float* __restrict__ out)
{
    const int b = blockIdx.x, o = threadIdx.x;
    float s = 0.f;
    for (int n = 0; n < TLEN; n++) s += g_Z[((size_t)b * TLEN + n) * OUTD + o];
    out[(size_t)BATCH * RES * OUTD + b * OUTD + o] = s;
}

/* ======================= launch ======================= */
extern "C" void kernel_launch(void* const* d_in, const int* in_sizes, int n_in,
                              void* d_out, int out_size)
{
    const float* input  = (const float*)d_in[0];
    const float* target = (const float*)d_in[1];
    const float* W_res  = (const float*)d_in[2];
    const float* W_in   = (const float*)d_in[3];
    const float* lam    = (const float*)d_in[4];
    float* out = (float*)d_out;

    cudaFuncSetAttribute(tc_kernel, cudaFuncAttributeMaxDynamicSharedMemorySize, SMEM_DYN);

    /* 0. split+transpose weights, split input */
    split_trans_kernel<<<dim3(RES / 32, RES / 32), dim3(32, 8)>>>(W_res, RES, RES, 0);
    split_trans_kernel<<<dim3(RES / 32, INDIM / 32), dim3(32, 8)>>>(W_in, INDIM, RES, 1);
    split_input_kernel<<<(NROWS * INDIM) / 256, 256>>>(input);

    /* 1. input projection */
    tc_kernel<<<dim3(RES / 128, NROWS / 128), 512, SMEM_DYN>>>(2, 0, 0, nullptr);

    /* 2. reservoir */
    init0_kernel<<<(MROWS * RES) / 256, 256>>>();
    int flip = 0;
    for (int s = 1; s <= 5; s++) {
        tc_kernel<<<dim3(RES / 128, MROWS / 128), 512, SMEM_DYN>>>(0, s, flip, nullptr);
        flip ^= 1;
    }

    /* 3. gram: 10 lower tiles + coalesced mirror */
    tc_kernel<<<dim3(10, 1, BATCH), 512, SMEM_DYN>>>(1, 0, 0, lam);
    mirror_kernel<<<dim3(16, 16, BATCH), dim3(32, 8)>>>();

    /* 4. batched blocked Cholesky */
    for (int p = 0; p < 8; p++) {
        chol_panel_kernel<<<BATCH, 256>>>(p);
        if (p < 7) {
            int mt = 7 - p;
            chol_update_kernel<<<dim3(mt * (mt + 1) / 2, BATCH), 256>>>(p);
        }
    }

    /* 4b. transpose L for coalesced forward solve */
    transL_kernel<<<dim3(16, 16, BATCH), dim3(32, 8)>>>();

    /* 5. triangular solves */
    solve_kernel<<<BATCH, 512>>>(target);

    /* 6. readout */
    wout_kernel<<<dim3(RES / 128, BATCH), 256>>>(out);
    bias_kernel<<<BATCH, 64>>>(out);

    (void)in_sizes; (void)n_in; (void)out_size;
}

// round 8
// speedup vs baseline: 1.7745x; 1.0189x over previous
#include <cuda_runtime.h>
#include <cuda_fp16.h>
#include <math.h>
#include <stdint.h>

#define BATCH 32
#define TLEN  512
#define INDIM 128
#define RES   2048
#define OUTD  64
#define NWIN  128
#define MROWS (BATCH*NWIN)   /* 4096  reservoir rows (b,w) */
#define NROWS (BATCH*TLEN)   /* 16384 time rows (b,t)      */

/* ---------------- scratch (device globals; no allocations) ---------------- */
__device__ float g_inproj[NROWS * RES];    /* input @ W_in (fp32)   128 MB */
__device__ float g_S0[MROWS * RES];        /* state ping (fp32)      32 MB */
__device__ float g_S1[MROWS * RES];        /* state pong (fp32)      32 MB */
__device__ float g_rs[NROWS * RES];        /* reservoir states      128 MB */
__device__ float g_A[BATCH * TLEN * TLEN]; /* gram matrices          32 MB */
__device__ float g_LT[BATCH * TLEN * TLEN];/* L transposed           32 MB */
__device__ float g_Z[BATCH * TLEN * OUTD]; /* solve result            4 MB */
/* fp16 split planes */
__device__ half g_Shi0[MROWS * RES], g_Slo0[MROWS * RES];
__device__ half g_Shi1[MROWS * RES], g_Slo1[MROWS * RES];
__device__ half g_rshi[NROWS * RES], g_rslo[NROWS * RES];
__device__ half g_Whi[RES * RES],   g_Wlo[RES * RES];       /* WresT     */
__device__ half g_WinHi[RES * INDIM], g_WinLo[RES * INDIM]; /* WinT      */
__device__ half g_xhi[NROWS * INDIM], g_xlo[NROWS * INDIM]; /* input     */

/* ====================== helpers ====================== */
__device__ __forceinline__ uint32_t smem_u32(const void* p) {
    uint32_t a;
    asm("{ .reg .u64 t; cvta.to.shared.u64 t, %1; cvt.u32.u64 %0, t; }" : "=r"(a) : "l"(p));
    return a;
}
__device__ __forceinline__ void cpasync16(uint32_t dst, const void* src) {
    asm volatile("cp.async.cg.shared.global [%0], [%1], 16;" :: "r"(dst), "l"(src));
}
__device__ __forceinline__ void cp_commit() { asm volatile("cp.async.commit_group;" ::: "memory"); }
__device__ __forceinline__ void cp_wait1()  { asm volatile("cp.async.wait_group 1;" ::: "memory"); }
__device__ __forceinline__ void cp_wait0()  { asm volatile("cp.async.wait_group 0;" ::: "memory"); }

__device__ __forceinline__ void ldsm4(uint32_t* r, uint32_t addr) {
    asm volatile("ldmatrix.sync.aligned.m8n8.x4.shared.b16 {%0,%1,%2,%3}, [%4];"
        : "=r"(r[0]), "=r"(r[1]), "=r"(r[2]), "=r"(r[3]) : "r"(addr));
}
__device__ __forceinline__ void mma16816(float* d, const uint32_t* a, uint32_t b0, uint32_t b1) {
    asm volatile(
        "mma.sync.aligned.m16n8k16.row.col.f32.f16.f16.f32 "
        "{%0,%1,%2,%3},{%4,%5,%6,%7},{%8,%9},{%0,%1,%2,%3};"
        : "+f"(d[0]), "+f"(d[1]), "+f"(d[2]), "+f"(d[3])
        : "r"(a[0]), "r"(a[1]), "r"(a[2]), "r"(a[3]), "r"(b0), "r"(b1));
}
__device__ __forceinline__ void split16(float f, half& h, half& l) {
    h = __float2half_rn(f);
    l = __float2half_rn(f - __half2float(h));
}

/* ============ fp16x3 GEMM kernel (mma.sync m16n8k16) ======================
   256 threads, 64x128 CTA tile (warp grid 2x4, 32x32 per warp).
   32-k chunks, 3 SMEM stages, ONE barrier per chunk, 2-chunk prefetch.
   Stage: Ahi(4K) Alo(4K) Bhi(8K) Blo(8K) = 24KB; 3 stages = 72KB.
   Rows are 64B (4x16B segs); swizzle seg' = seg ^ ((row>>1)&3).
   2 CTAs/SM (regs capped at 128 by launch_bounds).                         */
#define A_PLANE 4096
#define B_PLANE 8192
#define STAGE_B 24576
#define SMEM_DYN (3*STAGE_B)   /* 73728 */

__global__ __launch_bounds__(256, 2) void tc_kernel(
    int mode, int s, int flip, const float* __restrict__ lam)
{
    extern __shared__ char smem[];
    const uint32_t smem_u = smem_u32(smem);

    const int tid = threadIdx.x;
    const int wid = tid >> 5, lane = tid & 31;
    const int gid = lane >> 2, tig = lane & 3;
    const int m = lane >> 3, l7 = lane & 7;
    const int warpM = wid >> 2, warpN = wid & 3;   /* 2 x 4 warps */
    const int rowBase = warpM * 32, colBase = warpN * 32;

    int row0, col0;
    if (mode == 1) {
        /* 20 lower tiles of 8(64-row) x 4(128-col) grid: keep ri >= 2*cj */
        int x = blockIdx.x, cj, ri;
        if (x < 8)       { cj = 0; ri = x; }
        else if (x < 14) { cj = 1; ri = x - 6; }
        else if (x < 18) { cj = 2; ri = x - 10; }
        else             { cj = 3; ri = x - 12; }
        row0 = ri * 64; col0 = cj * 128;
    } else {
        row0 = blockIdx.y * 64; col0 = blockIdx.x * 128;
    }

    const half *Ahi, *Alo, *Bhi, *Blo; int K;
    if (mode == 0) {
        Ahi = flip ? g_Shi1 : g_Shi0; Alo = flip ? g_Slo1 : g_Slo0;
        Bhi = g_Whi; Blo = g_Wlo; K = RES;
    } else if (mode == 1) {
        size_t base = (size_t)blockIdx.z * TLEN * RES;
        Ahi = g_rshi + base; Alo = g_rslo + base;
        Bhi = Ahi; Blo = Alo; K = RES;
    } else {
        Ahi = g_xhi; Alo = g_xlo; Bhi = g_WinHi; Blo = g_WinLo; K = INDIM;
    }
    const int nIter = K >> 5;   /* 32-k chunks */

    float acc[2][4][4] = {};

    /* per-lane LDSM address components */
    uint32_t aRB[2], aX[2], bRB[2], bX[2];
    #pragma unroll
    for (int mt = 0; mt < 2; mt++) {
        uint32_t r = rowBase + mt * 16 + (m & 1) * 8 + l7;
        aRB[mt] = r * 64; aX[mt] = (r >> 1) & 3;
    }
    #pragma unroll
    for (int np = 0; np < 2; np++) {
        uint32_t n = colBase + (np * 2 + (m >> 1)) * 8 + l7;
        bRB[np] = n * 64; bX[np] = (n >> 1) & 3;
    }
    const uint32_t amk = (uint32_t)(m >> 1);
    const uint32_t bmk = (uint32_t)(m & 1);

    /* ---- loader: 1536 16B segs per 32-k chunk, 6 per thread ---- */
    auto load_chunk = [&](int it, int stage) {
        const int k0 = it << 5;
        const uint32_t sb = smem_u + (uint32_t)stage * STAGE_B;
        #pragma unroll
        for (int q = 0; q < 6; q++) {
            int idx = tid + q * 256;
            if (idx < 512) {                       /* A planes */
                int p = (idx >> 8) & 1, r = (idx >> 2) & 63, c = idx & 3;
                const half* gp = p ? Alo : Ahi;
                const half* src = gp + (size_t)(row0 + r) * K + k0 + c * 8;
                uint32_t dst = sb + (uint32_t)p * A_PLANE
                             + (uint32_t)r * 64 + (uint32_t)((c ^ ((r >> 1) & 3)) * 16);
                cpasync16(dst, src);
            } else {                               /* B planes */
                int j = idx - 512;
                int p = (j >> 9) & 1, r = (j >> 2) & 127, c = j & 3;
                const half* gp = p ? Blo : Bhi;
                const half* src = gp + (size_t)(col0 + r) * K + k0 + c * 8;
                uint32_t dst = sb + 2 * A_PLANE + (uint32_t)p * B_PLANE
                             + (uint32_t)r * 64 + (uint32_t)((c ^ ((r >> 1) & 3)) * 16);
                cpasync16(dst, src);
            }
        }
    };

    load_chunk(0, 0);
    cp_commit();
    if (nIter > 1) { load_chunk(1, 1); cp_commit(); }

    for (int it = 0; it < nIter; ++it) {
        if (it + 1 < nIter) cp_wait1(); else cp_wait0();
        __syncthreads();
        if (it + 2 < nIter) { load_chunk(it + 2, (it + 2) % 3); cp_commit(); }

        const uint32_t sb = smem_u + (uint32_t)(it % 3) * STAGE_B;
        const uint32_t pAh = sb, pAl = sb + A_PLANE;
        const uint32_t pBh = sb + 2 * A_PLANE, pBl = pBh + B_PLANE;
        #pragma unroll
        for (int h16 = 0; h16 < 2; h16++) {
            uint32_t ah[2][4], al[2][4], bh[2][4], bl[2][4];
            #pragma unroll
            for (int mt = 0; mt < 2; mt++) {
                uint32_t off = aRB[mt] + (((h16 * 2 + amk) ^ aX[mt]) * 16);
                ldsm4(ah[mt], pAh + off);
                ldsm4(al[mt], pAl + off);
            }
            #pragma unroll
            for (int np = 0; np < 2; np++) {
                uint32_t off = bRB[np] + (((h16 * 2 + bmk) ^ bX[np]) * 16);
                ldsm4(bh[np], pBh + off);
                ldsm4(bl[np], pBl + off);
            }
            #pragma unroll
            for (int mt = 0; mt < 2; mt++)
                #pragma unroll
                for (int nt = 0; nt < 4; nt++) {
                    uint32_t b0h = bh[nt >> 1][(nt & 1) * 2], b1h = bh[nt >> 1][(nt & 1) * 2 + 1];
                    uint32_t b0l = bl[nt >> 1][(nt & 1) * 2], b1l = bl[nt >> 1][(nt & 1) * 2 + 1];
                    mma16816(acc[mt][nt], ah[mt], b0h, b1h);
                    mma16816(acc[mt][nt], ah[mt], b0l, b1l);
                    mma16816(acc[mt][nt], al[mt], b0h, b1h);
                }
        }
    }

    /* -------------------- epilogue (register -> global) -------------------- */
    float regc = 0.f;
    if (mode == 1) { float l = lam[0]; regc = log1pf(expf(l)); }
    const float* Sold = flip ? g_S1 : g_S0;
    float* Snew = flip ? g_S0 : g_S1;
    half* ShiN = flip ? g_Shi0 : g_Shi1;
    half* SloN = flip ? g_Slo0 : g_Slo1;

    #pragma unroll
    for (int mt = 0; mt < 2; mt++)
        #pragma unroll
        for (int nt = 0; nt < 4; nt++)
            #pragma unroll
            for (int h = 0; h < 2; h++) {
                int grow = row0 + rowBase + mt * 16 + gid + h * 8;
                int col = col0 + colBase + nt * 8 + tig * 2;
                float cx = acc[mt][nt][h * 2 + 0];
                float cy = acc[mt][nt][h * 2 + 1];
                if (mode == 0) {
                    int b = grow >> 7, w = grow & 127;
                    int t = 4 * w + s - 2;
                    float2 so = *(const float2*)&Sold[(size_t)grow * RES + col];
                    float2 u = make_float2(0.f, 0.f);
                    if (t >= 0) u = *(const float2*)&g_inproj[((size_t)(b << 9) + t) * RES + col];
                    float2 v;
                    v.x = 0.7f * so.x + 0.3f * sinf(cx + u.x);
                    v.y = 0.7f * so.y + 0.3f * sinf(cy + u.y);
                    *(float2*)&Snew[(size_t)grow * RES + col] = v;
                    half hx, lx, hy, ly;
                    split16(v.x, hx, lx); split16(v.y, hy, ly);
                    *(half2*)&ShiN[(size_t)grow * RES + col] = __halves2half2(hx, hy);
                    *(half2*)&SloN[(size_t)grow * RES + col] = __halves2half2(lx, ly);
                    if (s >= 2) {
                        size_t ro = ((size_t)(b << 9) + t) * RES + col;
                        *(float2*)&g_rs[ro] = v;
                        *(half2*)&g_rshi[ro] = __halves2half2(hx, hy);
                        *(half2*)&g_rslo[ro] = __halves2half2(lx, ly);
                    }
                } else if (mode == 1) {
                    float* Abm = g_A + (size_t)blockIdx.z * TLEN * TLEN;
                    float2 v;
                    v.x = cx + 1.0f + ((grow == col + 0) ? regc : 0.f);
                    v.y = cy + 1.0f + ((grow == col + 1) ? regc : 0.f);
                    *(float2*)&Abm[(size_t)grow * TLEN + col] = v;
                } else {
                    *(float2*)&g_inproj[(size_t)grow * RES + col] = make_float2(cx, cy);
                }
            }
}

/* ============ split+transpose weights: dst[c][r] = split(src[r][c]) ======= */
__global__ void split_trans_kernel(const float* __restrict__ src, int rows, int cols, int which)
{
    half* dh = which ? g_WinHi : g_Whi;
    half* dl = which ? g_WinLo : g_Wlo;
    __shared__ float t[32][33];
    int c0 = blockIdx.x * 32, r0 = blockIdx.y * 32;
    for (int j = threadIdx.y; j < 32; j += 8)
        t[j][threadIdx.x] = src[(size_t)(r0 + j) * cols + c0 + threadIdx.x];
    __syncthreads();
    for (int j = threadIdx.y; j < 32; j += 8) {
        float f = t[threadIdx.x][j];
        half h, l; split16(f, h, l);
        size_t o = (size_t)(c0 + j) * rows + r0 + threadIdx.x;
        dh[o] = h; dl[o] = l;
    }
}

/* ============ split input rows (no transpose) ============================= */
__global__ void split_input_kernel(const float* __restrict__ src)
{
    int idx = blockIdx.x * 256 + threadIdx.x;
    float f = src[idx];
    half h, l; split16(f, h, l);
    g_xhi[idx] = h; g_xlo[idx] = l;
}

/* =================== step s=0 (state was zero) ============================ */
__global__ __launch_bounds__(256) void init0_kernel()
{
    int idx = blockIdx.x * 256 + threadIdx.x;
    int row = idx >> 11, qq = idx & 2047;
    int b = row >> 7, w = row & 127;
    int t = 4 * w - 2;
    float v = 0.f;
    if (t >= 0) v = 0.3f * sinf(g_inproj[((size_t)(b << 9) + t) * RES + qq]);
    g_S0[idx] = v;
    half h, l; split16(v, h, l);
    g_Shi0[idx] = h; g_Slo0[idx] = l;
}

/* ============ mirror upper 128-blocks of gram from lower ================== */
__global__ void mirror_kernel()
{
    int r0 = blockIdx.y * 32, c0 = blockIdx.x * 32;
    if ((r0 >> 7) >= (c0 >> 7)) return;
    float* Ab = g_A + (size_t)blockIdx.z * TLEN * TLEN;
    __shared__ float t[32][33];
    for (int j = threadIdx.y; j < 32; j += 8)
        t[j][threadIdx.x] = Ab[(size_t)(c0 + j) * TLEN + r0 + threadIdx.x];
    __syncthreads();
    for (int j = threadIdx.y; j < 32; j += 8)
        Ab[(size_t)(r0 + j) * TLEN + c0 + threadIdx.x] = t[threadIdx.x][j];
}

/* ====== transpose Cholesky factors: g_LT[b][j][i] = g_A[b][i][j] ========== */
__global__ void transL_kernel()
{
    const int b = blockIdx.z;
    const float* src = g_A + (size_t)b * TLEN * TLEN;
    float* dst = g_LT + (size_t)b * TLEN * TLEN;
    __shared__ float t[32][33];
    int c0 = blockIdx.x * 32, r0 = blockIdx.y * 32;
    for (int j = threadIdx.y; j < 32; j += 8)
        t[j][threadIdx.x] = src[(size_t)(r0 + j) * TLEN + c0 + threadIdx.x];
    __syncthreads();
    for (int j = threadIdx.y; j < 32; j += 8)
        dst[(size_t)(c0 + j) * TLEN + r0 + threadIdx.x] = t[threadIdx.x][j];
}

/* ============ blocked Cholesky, NB=64 ===================================== */
__global__ __launch_bounds__(256) void chol_panel_kernel(int p)
{
    const int b = blockIdx.x;
    float* Ab = g_A + (size_t)b * TLEN * TLEN;
    const int jb = p * 64;
    __shared__ float L11[64][65];
    const int tid = threadIdx.x;
    for (int idx = tid; idx < 64 * 64; idx += 256) {
        int r = idx >> 6, c = idx & 63;
        L11[r][c] = Ab[(jb + r) * TLEN + jb + c];
    }
    __syncthreads();
    for (int k = 0; k < 64; k++) {
        if (tid == 0) L11[k][k] = sqrtf(L11[k][k]);
        __syncthreads();
        if (tid > k && tid < 64) L11[tid][k] /= L11[k][k];
        __syncthreads();
        for (int idx = tid; idx < 64 * 64; idx += 256) {
            int r = idx >> 6, c = idx & 63;
            if (r > k && c > k && c <= r) L11[r][c] -= L11[r][k] * L11[c][k];
        }
        __syncthreads();
    }
    for (int idx = tid; idx < 64 * 64; idx += 256) {
        int r = idx >> 6, c = idx & 63;
        if (c <= r) Ab[(jb + r) * TLEN + jb + c] = L11[r][c];
    }
    __syncthreads();
    const int mrows = TLEN - jb - 64;
    for (int r = tid; r < mrows; r += 256) {
        int i = jb + 64 + r;
        float a[64];
        #pragma unroll
        for (int c = 0; c < 64; c++) a[c] = Ab[i * TLEN + jb + c];
        #pragma unroll
        for (int k = 0; k < 64; k++) {
            float sv = a[k];
            #pragma unroll
            for (int q = 0; q < k; q++) sv -= a[q] * L11[k][q];
            a[k] = sv / L11[k][k];
        }
        #pragma unroll
        for (int c = 0; c < 64; c++) Ab[i * TLEN + jb + c] = a[c];
    }
}

__global__ __launch_bounds__(256) void chol_update_kernel(int p)
{
    const int jb = p * 64 + 64;
    int idx = blockIdx.x;
    int ti = 0;
    while ((ti + 1) * (ti + 2) / 2 <= idx) ti++;
    int tj = idx - ti * (ti + 1) / 2;
    const int b = blockIdx.y;
    float* Ab = g_A + (size_t)b * TLEN * TLEN;
    const int r0 = jb + ti * 64, c0 = jb + tj * 64;
    __shared__ float La[64][65], Lb[64][65];
    const int tid = threadIdx.x;
    for (int q = tid; q < 64 * 64; q += 256) {
        int r = q >> 6, c = q & 63;
        La[r][c] = Ab[(r0 + r) * TLEN + p * 64 + c];
        Lb[r][c] = Ab[(c0 + r) * TLEN + p * 64 + c];
    }
    __syncthreads();
    const int tx = tid & 15, ty = tid >> 4;
    float acc[4][4] = {};
    #pragma unroll
    for (int k = 0; k < 64; k++) {
        float ar[4], bc[4];
        #pragma unroll
        for (int i = 0; i < 4; i++) ar[i] = La[ty * 4 + i][k];
        #pragma unroll
        for (int j = 0; j < 4; j++) bc[j] = Lb[tx * 4 + j][k];
        #pragma unroll
        for (int i = 0; i < 4; i++)
            #pragma unroll
            for (int j = 0; j < 4; j++)
                acc[i][j] += ar[i] * bc[j];
    }
    #pragma unroll
    for (int i = 0; i < 4; i++)
        #pragma unroll
        for (int j = 0; j < 4; j++)
            Ab[(r0 + ty * 4 + i) * TLEN + c0 + tx * 4 + j] -= acc[i][j];
}

/* ============ triangular solves, 64 RHS in registers ====================== */
__global__ __launch_bounds__(512) void solve_kernel(const float* __restrict__ Y)
{
    const int b = blockIdx.x;
    const int i = threadIdx.x;
    const float* __restrict__ Ab = g_A + (size_t)b * TLEN * TLEN;
    const float* __restrict__ Lt = g_LT + (size_t)b * TLEN * TLEN;
    float acc[OUTD];
    #pragma unroll
    for (int o = 0; o < OUTD; o++) acc[o] = Y[((size_t)b * TLEN + i) * OUTD + o];
    __shared__ float zrow[OUTD];
    for (int j = 0; j < TLEN; j++) {
        if (i == j) {
            float dinv = 1.f / Ab[j * TLEN + j];
            #pragma unroll
            for (int o = 0; o < OUTD; o++) { acc[o] *= dinv; zrow[o] = acc[o]; }
        }
        __syncthreads();
        if (i > j) {
            float lij = Lt[j * TLEN + i];
            #pragma unroll
            for (int o = 0; o < OUTD; o++) acc[o] -= lij * zrow[o];
        }
        __syncthreads();
    }
    for (int j = TLEN - 1; j >= 0; j--) {
        if (i == j) {
            float dinv = 1.f / Ab[j * TLEN + j];
            #pragma unroll
            for (int o = 0; o < OUTD; o++) { acc[o] *= dinv; zrow[o] = acc[o]; }
        }
        __syncthreads();
        if (i < j) {
            float lji = Ab[j * TLEN + i];
            #pragma unroll
            for (int o = 0; o < OUTD; o++) acc[o] -= lji * zrow[o];
        }
        __syncthreads();
    }
    #pragma unroll
    for (int o = 0; o < OUTD; o++) g_Z[((size_t)b * TLEN + i) * OUTD + o] = acc[o];
}

/* ============ W = Xb^T Z  (2048 x 64, K=512) ============================== */
__global__ __launch_bounds__(256) void wout_kernel(float* __restrict__ out)
{
    const int b = blockIdx.y;
    const float* __restrict__ X = g_rs + (size_t)b * TLEN * RES;
    const float* __restrict__ Zb = g_Z + (size_t)b * TLEN * OUTD;
    const int d0 = blockIdx.x * 128;
    __shared__ float As2[16][132];
    __shared__ float Bs2[16][68];
    const int tid = threadIdx.x;
    const int lr = tid >> 4, lc = (tid & 15) * 4;
    const int ty = tid >> 4, tx = tid & 15;
    float acc[8][4] = {};
    for (int k0 = 0; k0 < TLEN; k0 += 16) {
        *(float4*)&As2[lr][lc]      = *(const float4*)&X[(size_t)(k0 + lr) * RES + d0 + lc];
        *(float4*)&As2[lr][lc + 64] = *(const float4*)&X[(size_t)(k0 + lr) * RES + d0 + lc + 64];
        *(float4*)&Bs2[lr][lc]      = *(const float4*)&Zb[(k0 + lr) * OUTD + lc];
        __syncthreads();
        #pragma unroll
        for (int k = 0; k < 16; k++) {
            float fa[8], fb[4];
            *(float4*)&fa[0] = *(const float4*)&As2[k][ty * 8];
            *(float4*)&fa[4] = *(const float4*)&As2[k][ty * 8 + 4];
            *(float4*)&fb[0] = *(const float4*)&Bs2[k][tx * 4];
            #pragma unroll
            for (int i = 0; i < 8; i++)
                #pragma unroll
                for (int j = 0; j < 4; j++)
                    acc[i][j] += fa[i] * fb[j];
        }
        __syncthreads();
    }
    #pragma unroll
    for (int i = 0; i < 8; i++)
        #pragma unroll
        for (int j = 0; j < 4; j++)
            out[((size_t)b * RES + d0 + ty * 8 + i) * OUTD + tx * 4 + j] = acc[i][j];
}

__global__ void bias_kernel(float* __restrict__ out)
{
    const int b = blockIdx.x, o = threadIdx.x;
    float s = 0.f;
    for (int n = 0; n < TLEN; n++) s += g_Z[((size_t)b * TLEN + n) * OUTD + o];
    out[(size_t)BATCH * RES * OUTD + b * OUTD + o] = s;
}

/* ======================= launch ======================= */
extern "C" void kernel_launch(void* const* d_in, const int* in_sizes, int n_in,
                              void* d_out, int out_size)
{
    const float* input  = (const float*)d_in[0];
    const float* target = (const float*)d_in[1];
    const float* W_res  = (const float*)d_in[2];
    const float* W_in   = (const float*)d_in[3];
    const float* lam    = (const float*)d_in[4];
    float* out = (float*)d_out;

    cudaFuncSetAttribute(tc_kernel, cudaFuncAttributeMaxDynamicSharedMemorySize, SMEM_DYN);

    /* 0. split+transpose weights, split input */
    split_trans_kernel<<<dim3(RES / 32, RES / 32), dim3(32, 8)>>>(W_res, RES, RES, 0);
    split_trans_kernel<<<dim3(RES / 32, INDIM / 32), dim3(32, 8)>>>(W_in, INDIM, RES, 1);
    split_input_kernel<<<(NROWS * INDIM) / 256, 256>>>(input);

    /* 1. input projection */
    tc_kernel<<<dim3(RES / 128, NROWS / 64), 256, SMEM_DYN>>>(2, 0, 0, nullptr);

    /* 2. reservoir */
    init0_kernel<<<(MROWS * RES) / 256, 256>>>();
    int flip = 0;
    for (int s = 1; s <= 5; s++) {
        tc_kernel<<<dim3(RES / 128, MROWS / 64), 256, SMEM_DYN>>>(0, s, flip, nullptr);
        flip ^= 1;
    }

    /* 3. gram: 20 lower (64x128) tiles + coalesced mirror */
    tc_kernel<<<dim3(20, 1, BATCH), 256, SMEM_DYN>>>(1, 0, 0, lam);
    mirror_kernel<<<dim3(16, 16, BATCH), dim3(32, 8)>>>();

    /* 4. batched blocked Cholesky */
    for (int p = 0; p < 8; p++) {
        chol_panel_kernel<<<BATCH, 256>>>(p);
        if (p < 7) {
            int mt = 7 - p;
            chol_update_kernel<<<dim3(mt * (mt + 1) / 2, BATCH), 256>>>(p);
        }
    }

    /* 4b. transpose L for coalesced forward solve */
    transL_kernel<<<dim3(16, 16, BATCH), dim3(32, 8)>>>();

    /* 5. triangular solves */
    solve_kernel<<<BATCH, 512>>>(target);

    /* 6. readout */
    wout_kernel<<<dim3(RES / 128, BATCH), 256>>>(out);
    bias_kernel<<<BATCH, 64>>>(out);

    (void)in_sizes; (void)n_in; (void)out_size;
}

// round 9
// speedup vs baseline: 1.7961x; 1.0121x over previous
#include <cuda_runtime.h>
#include <cuda_fp16.h>
#include <math.h>
#include <stdint.h>

#define BATCH 32
#define TLEN  512
#define INDIM 128
#define RES   2048
#define OUTD  64
#define NWIN  128
#define MROWS (BATCH*NWIN)   /* 4096  reservoir rows (b,w) */
#define NROWS (BATCH*TLEN)   /* 16384 time rows (b,t)      */

/* ---------------- scratch (device globals; no allocations) ---------------- */
__device__ float g_inproj[NROWS * RES];    /* input @ W_in (fp32)   128 MB */
__device__ float g_S0[MROWS * RES];        /* state ping (fp32)      32 MB */
__device__ float g_S1[MROWS * RES];        /* state pong (fp32)      32 MB */
__device__ float g_rs[NROWS * RES];        /* reservoir states      128 MB */
__device__ float g_A[BATCH * TLEN * TLEN]; /* gram matrices          32 MB */
__device__ float g_LT[BATCH * TLEN * TLEN];/* L transposed           32 MB */
__device__ float g_Z[BATCH * TLEN * OUTD]; /* solve result            4 MB */
/* fp16 split planes */
__device__ half g_Shi0[MROWS * RES], g_Slo0[MROWS * RES];
__device__ half g_Shi1[MROWS * RES], g_Slo1[MROWS * RES];
__device__ half g_rshi[NROWS * RES], g_rslo[NROWS * RES];
__device__ half g_Whi[RES * RES],   g_Wlo[RES * RES];       /* WresT     */
__device__ half g_WinHi[RES * INDIM], g_WinLo[RES * INDIM]; /* WinT      */
__device__ half g_xhi[NROWS * INDIM], g_xlo[NROWS * INDIM]; /* input     */

/* ====================== helpers ====================== */
__device__ __forceinline__ uint32_t smem_u32(const void* p) {
    uint32_t a;
    asm("{ .reg .u64 t; cvta.to.shared.u64 t, %1; cvt.u32.u64 %0, t; }" : "=r"(a) : "l"(p));
    return a;
}
__device__ __forceinline__ void cpasync16(uint32_t dst, const void* src) {
    asm volatile("cp.async.cg.shared.global [%0], [%1], 16;" :: "r"(dst), "l"(src));
}
__device__ __forceinline__ void cp_commit() { asm volatile("cp.async.commit_group;" ::: "memory"); }
__device__ __forceinline__ void cp_wait1()  { asm volatile("cp.async.wait_group 1;" ::: "memory"); }
__device__ __forceinline__ void cp_wait0()  { asm volatile("cp.async.wait_group 0;" ::: "memory"); }

__device__ __forceinline__ void ldsm4(uint32_t* r, uint32_t addr) {
    asm volatile("ldmatrix.sync.aligned.m8n8.x4.shared.b16 {%0,%1,%2,%3}, [%4];"
        : "=r"(r[0]), "=r"(r[1]), "=r"(r[2]), "=r"(r[3]) : "r"(addr));
}
__device__ __forceinline__ void mma16816(float* d, const uint32_t* a, uint32_t b0, uint32_t b1) {
    asm volatile(
        "mma.sync.aligned.m16n8k16.row.col.f32.f16.f16.f32 "
        "{%0,%1,%2,%3},{%4,%5,%6,%7},{%8,%9},{%0,%1,%2,%3};"
        : "+f"(d[0]), "+f"(d[1]), "+f"(d[2]), "+f"(d[3])
        : "r"(a[0]), "r"(a[1]), "r"(a[2]), "r"(a[3]), "r"(b0), "r"(b1));
}
__device__ __forceinline__ void split16(float f, half& h, half& l) {
    h = __float2half_rn(f);
    l = __float2half_rn(f - __half2float(h));
}

/* ============ fp16x3 GEMM kernel (mma.sync m16n8k16) ======================
   256 threads, 128x128 CTA tile (warp grid 2x4, 64x32 per warp).
   32-k chunks, 3 SMEM stages, ONE barrier per chunk, 2-chunk prefetch.
   Stage: Ahi(8K) Alo(8K) Bhi(8K) Blo(8K) = 32KB; 3 stages = 96KB.
   Rows are 64B (4x16B segs); swizzle seg' = seg ^ ((row>>1)&3).
   2 CTAs/SM (regs capped at 128 by launch_bounds).                         */
#define A_PLANE 8192
#define B_PLANE 8192
#define STAGE_B 32768
#define SMEM_DYN (3*STAGE_B)   /* 98304 */

__global__ __launch_bounds__(256, 2) void tc_kernel(
    int mode, int s, int flip, const float* __restrict__ lam)
{
    extern __shared__ char smem[];
    const uint32_t smem_u = smem_u32(smem);

    const int tid = threadIdx.x;
    const int wid = tid >> 5, lane = tid & 31;
    const int gid = lane >> 2, tig = lane & 3;
    const int m = lane >> 3, l7 = lane & 7;
    const int warpM = wid >> 2, warpN = wid & 3;   /* 2 x 4 warps */
    const int rowBase = warpM * 64, colBase = warpN * 32;

    int row0, col0;
    if (mode == 1) {
        /* 10 lower tiles of 4x4 grid of 128x128 */
        int x = blockIdx.x, ti = 0;
        while ((ti + 1) * (ti + 2) / 2 <= x) ti++;
        int tj = x - ti * (ti + 1) / 2;
        row0 = ti * 128; col0 = tj * 128;
    } else {
        row0 = blockIdx.y * 128; col0 = blockIdx.x * 128;
    }

    const half *Ahi, *Alo, *Bhi, *Blo; int K;
    if (mode == 0) {
        Ahi = flip ? g_Shi1 : g_Shi0; Alo = flip ? g_Slo1 : g_Slo0;
        Bhi = g_Whi; Blo = g_Wlo; K = RES;
    } else if (mode == 1) {
        size_t base = (size_t)blockIdx.z * TLEN * RES;
        Ahi = g_rshi + base; Alo = g_rslo + base;
        Bhi = Ahi; Blo = Alo; K = RES;
    } else {
        Ahi = g_xhi; Alo = g_xlo; Bhi = g_WinHi; Blo = g_WinLo; K = INDIM;
    }
    const int nIter = K >> 5;   /* 32-k chunks */

    float acc[4][4][4] = {};

    /* per-lane LDSM address components */
    uint32_t aRB[4], aX[4], bRB[2], bX[2];
    #pragma unroll
    for (int mt = 0; mt < 4; mt++) {
        uint32_t r = rowBase + mt * 16 + (m & 1) * 8 + l7;
        aRB[mt] = r * 64; aX[mt] = (r >> 1) & 3;
    }
    #pragma unroll
    for (int np = 0; np < 2; np++) {
        uint32_t n = colBase + (np * 2 + (m >> 1)) * 8 + l7;
        bRB[np] = n * 64; bX[np] = (n >> 1) & 3;
    }
    const uint32_t amk = (uint32_t)(m >> 1);
    const uint32_t bmk = (uint32_t)(m & 1);

    /* ---- loader: 2048 16B segs per 32-k chunk, 8 per thread ---- */
    auto load_chunk = [&](int it, int stage) {
        const int k0 = it << 5;
        const uint32_t sb = smem_u + (uint32_t)stage * STAGE_B;
        #pragma unroll
        for (int q = 0; q < 8; q++) {
            int idx = tid + q * 256;
            int op = idx >> 10;                /* 0: A planes, 1: B planes */
            int j = idx & 1023;
            int p = j >> 9, r = (j >> 2) & 127, c = j & 3;
            const half* gp = op ? (p ? Blo : Bhi) : (p ? Alo : Ahi);
            int rowg = (op ? col0 : row0) + r;
            const half* src = gp + (size_t)rowg * K + k0 + c * 8;
            uint32_t dst = sb + (uint32_t)op * (2 * A_PLANE) + (uint32_t)p * A_PLANE
                         + (uint32_t)r * 64 + (uint32_t)((c ^ ((r >> 1) & 3)) * 16);
            cpasync16(dst, src);
        }
    };

    load_chunk(0, 0);
    cp_commit();
    if (nIter > 1) { load_chunk(1, 1); cp_commit(); }

    for (int it = 0; it < nIter; ++it) {
        if (it + 1 < nIter) cp_wait1(); else cp_wait0();
        __syncthreads();
        if (it + 2 < nIter) { load_chunk(it + 2, (it + 2) % 3); cp_commit(); }

        const uint32_t sb = smem_u + (uint32_t)(it % 3) * STAGE_B;
        const uint32_t pAh = sb, pAl = sb + A_PLANE;
        const uint32_t pBh = sb + 2 * A_PLANE, pBl = pBh + B_PLANE;
        #pragma unroll
        for (int h16 = 0; h16 < 2; h16++) {
            uint32_t bh[2][4], bl[2][4];
            #pragma unroll
            for (int np = 0; np < 2; np++) {
                uint32_t off = bRB[np] + (((h16 * 2 + bmk) ^ bX[np]) * 16);
                ldsm4(bh[np], pBh + off);
                ldsm4(bl[np], pBl + off);
            }
            #pragma unroll
            for (int mt = 0; mt < 4; mt++) {
                uint32_t ah[4], al[4];
                uint32_t off = aRB[mt] + (((h16 * 2 + amk) ^ aX[mt]) * 16);
                ldsm4(ah, pAh + off);
                ldsm4(al, pAl + off);
                #pragma unroll
                for (int nt = 0; nt < 4; nt++) {
                    uint32_t b0h = bh[nt >> 1][(nt & 1) * 2], b1h = bh[nt >> 1][(nt & 1) * 2 + 1];
                    uint32_t b0l = bl[nt >> 1][(nt & 1) * 2], b1l = bl[nt >> 1][(nt & 1) * 2 + 1];
                    mma16816(acc[mt][nt], ah, b0h, b1h);
                    mma16816(acc[mt][nt], ah, b0l, b1l);
                    mma16816(acc[mt][nt], al, b0h, b1h);
                }
            }
        }
    }

    /* -------------------- epilogue (register -> global) -------------------- */
    float regc = 0.f;
    if (mode == 1) { float l = lam[0]; regc = log1pf(expf(l)); }
    const float* Sold = flip ? g_S1 : g_S0;
    float* Snew = flip ? g_S0 : g_S1;
    half* ShiN = flip ? g_Shi0 : g_Shi1;
    half* SloN = flip ? g_Slo0 : g_Slo1;

    #pragma unroll
    for (int mt = 0; mt < 4; mt++)
        #pragma unroll
        for (int nt = 0; nt < 4; nt++)
            #pragma unroll
            for (int h = 0; h < 2; h++) {
                int grow = row0 + rowBase + mt * 16 + gid + h * 8;
                int col = col0 + colBase + nt * 8 + tig * 2;
                float cx = acc[mt][nt][h * 2 + 0];
                float cy = acc[mt][nt][h * 2 + 1];
                if (mode == 0) {
                    int b = grow >> 7, w = grow & 127;
                    int t = 4 * w + s - 2;
                    float2 so = *(const float2*)&Sold[(size_t)grow * RES + col];
                    float2 u = make_float2(0.f, 0.f);
                    if (t >= 0) u = *(const float2*)&g_inproj[((size_t)(b << 9) + t) * RES + col];
                    float2 v;
                    v.x = 0.7f * so.x + 0.3f * sinf(cx + u.x);
                    v.y = 0.7f * so.y + 0.3f * sinf(cy + u.y);
                    *(float2*)&Snew[(size_t)grow * RES + col] = v;
                    half hx, lx, hy, ly;
                    split16(v.x, hx, lx); split16(v.y, hy, ly);
                    *(half2*)&ShiN[(size_t)grow * RES + col] = __halves2half2(hx, hy);
                    *(half2*)&SloN[(size_t)grow * RES + col] = __halves2half2(lx, ly);
                    if (s >= 2) {
                        size_t ro = ((size_t)(b << 9) + t) * RES + col;
                        *(float2*)&g_rs[ro] = v;
                        *(half2*)&g_rshi[ro] = __halves2half2(hx, hy);
                        *(half2*)&g_rslo[ro] = __halves2half2(lx, ly);
                    }
                } else if (mode == 1) {
                    float* Abm = g_A + (size_t)blockIdx.z * TLEN * TLEN;
                    float2 v;
                    v.x = cx + 1.0f + ((grow == col + 0) ? regc : 0.f);
                    v.y = cy + 1.0f + ((grow == col + 1) ? regc : 0.f);
                    *(float2*)&Abm[(size_t)grow * TLEN + col] = v;
                } else {
                    *(float2*)&g_inproj[(size_t)grow * RES + col] = make_float2(cx, cy);
                }
            }
}

/* ============ split+transpose weights: dst[c][r] = split(src[r][c]) ======= */
__global__ void split_trans_kernel(const float* __restrict__ src, int rows, int cols, int which)
{
    half* dh = which ? g_WinHi : g_Whi;
    half* dl = which ? g_WinLo : g_Wlo;
    __shared__ float t[32][33];
    int c0 = blockIdx.x * 32, r0 = blockIdx.y * 32;
    for (int j = threadIdx.y; j < 32; j += 8)
        t[j][threadIdx.x] = src[(size_t)(r0 + j) * cols + c0 + threadIdx.x];
    __syncthreads();
    for (int j = threadIdx.y; j < 32; j += 8) {
        float f = t[threadIdx.x][j];
        half h, l; split16(f, h, l);
        size_t o = (size_t)(c0 + j) * rows + r0 + threadIdx.x;
        dh[o] = h; dl[o] = l;
    }
}

/* ============ split input rows (no transpose) ============================= */
__global__ void split_input_kernel(const float* __restrict__ src)
{
    int idx = blockIdx.x * 256 + threadIdx.x;
    float f = src[idx];
    half h, l; split16(f, h, l);
    g_xhi[idx] = h; g_xlo[idx] = l;
}

/* =================== step s=0 (state was zero) ============================ */
__global__ __launch_bounds__(256) void init0_kernel()
{
    int idx = blockIdx.x * 256 + threadIdx.x;
    int row = idx >> 11, qq = idx & 2047;
    int b = row >> 7, w = row & 127;
    int t = 4 * w - 2;
    float v = 0.f;
    if (t >= 0) v = 0.3f * sinf(g_inproj[((size_t)(b << 9) + t) * RES + qq]);
    g_S0[idx] = v;
    half h, l; split16(v, h, l);
    g_Shi0[idx] = h; g_Slo0[idx] = l;
}

/* ============ mirror upper 128-blocks of gram from lower ================== */
__global__ void mirror_kernel()
{
    int r0 = blockIdx.y * 32, c0 = blockIdx.x * 32;
    if ((r0 >> 7) >= (c0 >> 7)) return;
    float* Ab = g_A + (size_t)blockIdx.z * TLEN * TLEN;
    __shared__ float t[32][33];
    for (int j = threadIdx.y; j < 32; j += 8)
        t[j][threadIdx.x] = Ab[(size_t)(c0 + j) * TLEN + r0 + threadIdx.x];
    __syncthreads();
    for (int j = threadIdx.y; j < 32; j += 8)
        Ab[(size_t)(r0 + j) * TLEN + c0 + threadIdx.x] = t[threadIdx.x][j];
}

/* ====== transpose Cholesky factors: g_LT[b][j][i] = g_A[b][i][j] ========== */
__global__ void transL_kernel()
{
    const int b = blockIdx.z;
    const float* src = g_A + (size_t)b * TLEN * TLEN;
    float* dst = g_LT + (size_t)b * TLEN * TLEN;
    __shared__ float t[32][33];
    int c0 = blockIdx.x * 32, r0 = blockIdx.y * 32;
    for (int j = threadIdx.y; j < 32; j += 8)
        t[j][threadIdx.x] = src[(size_t)(r0 + j) * TLEN + c0 + threadIdx.x];
    __syncthreads();
    for (int j = threadIdx.y; j < 32; j += 8)
        dst[(size_t)(c0 + j) * TLEN + r0 + threadIdx.x] = t[threadIdx.x][j];
}

/* ============ blocked Cholesky, NB=64 ===================================== */
__global__ __launch_bounds__(256) void chol_panel_kernel(int p)
{
    const int b = blockIdx.x;
    float* Ab = g_A + (size_t)b * TLEN * TLEN;
    const int jb = p * 64;
    __shared__ float L11[64][65];
    const int tid = threadIdx.x;
    for (int idx = tid; idx < 64 * 64; idx += 256) {
        int r = idx >> 6, c = idx & 63;
        L11[r][c] = Ab[(jb + r) * TLEN + jb + c];
    }
    __syncthreads();
    for (int k = 0; k < 64; k++) {
        if (tid == 0) L11[k][k] = sqrtf(L11[k][k]);
        __syncthreads();
        if (tid > k && tid < 64) L11[tid][k] /= L11[k][k];
        __syncthreads();
        for (int idx = tid; idx < 64 * 64; idx += 256) {
            int r = idx >> 6, c = idx & 63;
            if (r > k && c > k && c <= r) L11[r][c] -= L11[r][k] * L11[c][k];
        }
        __syncthreads();
    }
    for (int idx = tid; idx < 64 * 64; idx += 256) {
        int r = idx >> 6, c = idx & 63;
        if (c <= r) Ab[(jb + r) * TLEN + jb + c] = L11[r][c];
    }
    __syncthreads();
    const int mrows = TLEN - jb - 64;
    for (int r = tid; r < mrows; r += 256) {
        int i = jb + 64 + r;
        float a[64];
        #pragma unroll
        for (int c = 0; c < 64; c++) a[c] = Ab[i * TLEN + jb + c];
        #pragma unroll
        for (int k = 0; k < 64; k++) {
            float sv = a[k];
            #pragma unroll
            for (int q = 0; q < k; q++) sv -= a[q] * L11[k][q];
            a[k] = sv / L11[k][k];
        }
        #pragma unroll
        for (int c = 0; c < 64; c++) Ab[i * TLEN + jb + c] = a[c];
    }
}

__global__ __launch_bounds__(256) void chol_update_kernel(int p)
{
    const int jb = p * 64 + 64;
    int idx = blockIdx.x;
    int ti = 0;
    while ((ti + 1) * (ti + 2) / 2 <= idx) ti++;
    int tj = idx - ti * (ti + 1) / 2;
    const int b = blockIdx.y;
    float* Ab = g_A + (size_t)b * TLEN * TLEN;
    const int r0 = jb + ti * 64, c0 = jb + tj * 64;
    __shared__ float La[64][65], Lb[64][65];
    const int tid = threadIdx.x;
    for (int q = tid; q < 64 * 64; q += 256) {
        int r = q >> 6, c = q & 63;
        La[r][c] = Ab[(r0 + r) * TLEN + p * 64 + c];
        Lb[r][c] = Ab[(c0 + r) * TLEN + p * 64 + c];
    }
    __syncthreads();
    const int tx = tid & 15, ty = tid >> 4;
    float acc[4][4] = {};
    #pragma unroll
    for (int k = 0; k < 64; k++) {
        float ar[4], bc[4];
        #pragma unroll
        for (int i = 0; i < 4; i++) ar[i] = La[ty * 4 + i][k];
        #pragma unroll
        for (int j = 0; j < 4; j++) bc[j] = Lb[tx * 4 + j][k];
        #pragma unroll
        for (int i = 0; i < 4; i++)
            #pragma unroll
            for (int j = 0; j < 4; j++)
                acc[i][j] += ar[i] * bc[j];
    }
    #pragma unroll
    for (int i = 0; i < 4; i++)
        #pragma unroll
        for (int j = 0; j < 4; j++)
            Ab[(r0 + ty * 4 + i) * TLEN + c0 + tx * 4 + j] -= acc[i][j];
}

/* ============ triangular solves, 64 RHS in registers ====================== */
__global__ __launch_bounds__(512) void solve_kernel(const float* __restrict__ Y)
{
    const int b = blockIdx.x;
    const int i = threadIdx.x;
    const float* __restrict__ Ab = g_A + (size_t)b * TLEN * TLEN;
    const float* __restrict__ Lt = g_LT + (size_t)b * TLEN * TLEN;
    float acc[OUTD];
    #pragma unroll
    for (int o = 0; o < OUTD; o++) acc[o] = Y[((size_t)b * TLEN + i) * OUTD + o];
    __shared__ float zrow[OUTD];
    for (int j = 0; j < TLEN; j++) {
        if (i == j) {
            float dinv = 1.f / Ab[j * TLEN + j];
            #pragma unroll
            for (int o = 0; o < OUTD; o++) { acc[o] *= dinv; zrow[o] = acc[o]; }
        }
        __syncthreads();
        if (i > j) {
            float lij = Lt[j * TLEN + i];
            #pragma unroll
            for (int o = 0; o < OUTD; o++) acc[o] -= lij * zrow[o];
        }
        __syncthreads();
    }
    for (int j = TLEN - 1; j >= 0; j--) {
        if (i == j) {
            float dinv = 1.f / Ab[j * TLEN + j];
            #pragma unroll
            for (int o = 0; o < OUTD; o++) { acc[o] *= dinv; zrow[o] = acc[o]; }
        }
        __syncthreads();
        if (i < j) {
            float lji = Ab[j * TLEN + i];
            #pragma unroll
            for (int o = 0; o < OUTD; o++) acc[o] -= lji * zrow[o];
        }
        __syncthreads();
    }
    #pragma unroll
    for (int o = 0; o < OUTD; o++) g_Z[((size_t)b * TLEN + i) * OUTD + o] = acc[o];
}

/* ============ W = Xb^T Z  (2048 x 64, K=512) ============================== */
__global__ __launch_bounds__(256) void wout_kernel(float* __restrict__ out)
{
    const int b = blockIdx.y;
    const float* __restrict__ X = g_rs + (size_t)b * TLEN * RES;
    const float* __restrict__ Zb = g_Z + (size_t)b * TLEN * OUTD;
    const int d0 = blockIdx.x * 128;
    __shared__ float As2[16][132];
    __shared__ float Bs2[16][68];
    const int tid = threadIdx.x;
    const int lr = tid >> 4, lc = (tid & 15) * 4;
    const int ty = tid >> 4, tx = tid & 15;
    float acc[8][4] = {};
    for (int k0 = 0; k0 < TLEN; k0 += 16) {
        *(float4*)&As2[lr][lc]      = *(const float4*)&X[(size_t)(k0 + lr) * RES + d0 + lc];
        *(float4*)&As2[lr][lc + 64] = *(const float4*)&X[(size_t)(k0 + lr) * RES + d0 + lc + 64];
        *(float4*)&Bs2[lr][lc]      = *(const float4*)&Zb[(k0 + lr) * OUTD + lc];
        __syncthreads();
        #pragma unroll
        for (int k = 0; k < 16; k++) {
            float fa[8], fb[4];
            *(float4*)&fa[0] = *(const float4*)&As2[k][ty * 8];
            *(float4*)&fa[4] = *(const float4*)&As2[k][ty * 8 + 4];
            *(float4*)&fb[0] = *(const float4*)&Bs2[k][tx * 4];
            #pragma unroll
            for (int i = 0; i < 8; i++)
                #pragma unroll
                for (int j = 0; j < 4; j++)
                    acc[i][j] += fa[i] * fb[j];
        }
        __syncthreads();
    }
    #pragma unroll
    for (int i = 0; i < 8; i++)
        #pragma unroll
        for (int j = 0; j < 4; j++)
            out[((size_t)b * RES + d0 + ty * 8 + i) * OUTD + tx * 4 + j] = acc[i][j];
}

__global__ void bias_kernel(float* __restrict__ out)
{
    const int b = blockIdx.x, o = threadIdx.x;
    float s = 0.f;
    for (int n = 0; n < TLEN; n++) s += g_Z[((size_t)b * TLEN + n) * OUTD + o];
    out[(size_t)BATCH * RES * OUTD + b * OUTD + o] = s;
}

/* ======================= launch ======================= */
extern "C" void kernel_launch(void* const* d_in, const int* in_sizes, int n_in,
                              void* d_out, int out_size)
{
    const float* input  = (const float*)d_in[0];
    const float* target = (const float*)d_in[1];
    const float* W_res  = (const float*)d_in[2];
    const float* W_in   = (const float*)d_in[3];
    const float* lam    = (const float*)d_in[4];
    float* out = (float*)d_out;

    cudaFuncSetAttribute(tc_kernel, cudaFuncAttributeMaxDynamicSharedMemorySize, SMEM_DYN);

    /* 0. split+transpose weights, split input */
    split_trans_kernel<<<dim3(RES / 32, RES / 32), dim3(32, 8)>>>(W_res, RES, RES, 0);
    split_trans_kernel<<<dim3(RES / 32, INDIM / 32), dim3(32, 8)>>>(W_in, INDIM, RES, 1);
    split_input_kernel<<<(NROWS * INDIM) / 256, 256>>>(input);

    /* 1. input projection */
    tc_kernel<<<dim3(RES / 128, NROWS / 128), 256, SMEM_DYN>>>(2, 0, 0, nullptr);

    /* 2. reservoir */
    init0_kernel<<<(MROWS * RES) / 256, 256>>>();
    int flip = 0;
    for (int s = 1; s <= 5; s++) {
        tc_kernel<<<dim3(RES / 128, MROWS / 128), 256, SMEM_DYN>>>(0, s, flip, nullptr);
        flip ^= 1;
    }

    /* 3. gram: 10 lower (128x128) tiles + coalesced mirror */
    tc_kernel<<<dim3(10, 1, BATCH), 256, SMEM_DYN>>>(1, 0, 0, lam);
    mirror_kernel<<<dim3(16, 16, BATCH), dim3(32, 8)>>>();

    /* 4. batched blocked Cholesky */
    for (int p = 0; p < 8; p++) {
        chol_panel_kernel<<<BATCH, 256>>>(p);
        if (p < 7) {
            int mt = 7 - p;
            chol_update_kernel<<<dim3(mt * (mt + 1) / 2, BATCH), 256>>>(p);
        }
    }

    /* 4b. transpose L for coalesced forward solve */
    transL_kernel<<<dim3(16, 16, BATCH), dim3(32, 8)>>>();

    /* 5. triangular solves */
    solve_kernel<<<BATCH, 512>>>(target);

    /* 6. readout */
    wout_kernel<<<dim3(RES / 128, BATCH), 256>>>(out);
    bias_kernel<<<BATCH, 64>>>(out);

    (void)in_sizes; (void)n_in; (void)out_size;
}

// round 10
// speedup vs baseline: 1.7962x; 1.0001x over previous
#include <cuda_runtime.h>
#include <cuda_fp16.h>
#include <math.h>
#include <stdint.h>

#define BATCH 32
#define TLEN  512
#define INDIM 128
#define RES   2048
#define OUTD  64
#define NWIN  128
#define MROWS (BATCH*NWIN)   /* 4096  reservoir rows (b,w) */
#define NROWS (BATCH*TLEN)   /* 16384 time rows (b,t)      */

/* ---------------- scratch (device globals; no allocations) ---------------- */
__device__ float g_A[BATCH * TLEN * TLEN]; /* gram matrices          32 MB */
__device__ float g_LT[BATCH * TLEN * TLEN];/* L transposed           32 MB */
__device__ float g_Z[BATCH * TLEN * OUTD]; /* solve result            4 MB */
/* fp16 split planes (hi+lo reconstructs fp32 to ~2^-22) */
__device__ half g_Shi0[MROWS * RES], g_Slo0[MROWS * RES];   /* state ping */
__device__ half g_Shi1[MROWS * RES], g_Slo1[MROWS * RES];   /* state pong */
__device__ half g_rshi[NROWS * RES], g_rslo[NROWS * RES];   /* rs states  */
__device__ half g_iphi[NROWS * RES], g_iplo[NROWS * RES];   /* inproj     */
__device__ half g_Whi[RES * RES],   g_Wlo[RES * RES];       /* WresT      */
__device__ half g_WinHi[RES * INDIM], g_WinLo[RES * INDIM]; /* WinT       */
__device__ half g_xhi[NROWS * INDIM], g_xlo[NROWS * INDIM]; /* input      */

/* ====================== helpers ====================== */
__device__ __forceinline__ uint32_t smem_u32(const void* p) {
    uint32_t a;
    asm("{ .reg .u64 t; cvta.to.shared.u64 t, %1; cvt.u32.u64 %0, t; }" : "=r"(a) : "l"(p));
    return a;
}
__device__ __forceinline__ void cpasync16(uint32_t dst, const void* src) {
    asm volatile("cp.async.cg.shared.global [%0], [%1], 16;" :: "r"(dst), "l"(src));
}
__device__ __forceinline__ void cp_commit() { asm volatile("cp.async.commit_group;" ::: "memory"); }
__device__ __forceinline__ void cp_wait1()  { asm volatile("cp.async.wait_group 1;" ::: "memory"); }
__device__ __forceinline__ void cp_wait0()  { asm volatile("cp.async.wait_group 0;" ::: "memory"); }

__device__ __forceinline__ void ldsm4(uint32_t* r, uint32_t addr) {
    asm volatile("ldmatrix.sync.aligned.m8n8.x4.shared.b16 {%0,%1,%2,%3}, [%4];"
        : "=r"(r[0]), "=r"(r[1]), "=r"(r[2]), "=r"(r[3]) : "r"(addr));
}
__device__ __forceinline__ void mma16816(float* d, const uint32_t* a, uint32_t b0, uint32_t b1) {
    asm volatile(
        "mma.sync.aligned.m16n8k16.row.col.f32.f16.f16.f32 "
        "{%0,%1,%2,%3},{%4,%5,%6,%7},{%8,%9},{%0,%1,%2,%3};"
        : "+f"(d[0]), "+f"(d[1]), "+f"(d[2]), "+f"(d[3])
        : "r"(a[0]), "r"(a[1]), "r"(a[2]), "r"(a[3]), "r"(b0), "r"(b1));
}
__device__ __forceinline__ void split16(float f, half& h, half& l) {
    h = __float2half_rn(f);
    l = __float2half_rn(f - __half2float(h));
}
__device__ __forceinline__ float2 rec2(half2 h, half2 l) {   /* hi+lo pairs */
    float2 fh = __half22float2(h), fl = __half22float2(l);
    return make_float2(fh.x + fl.x, fh.y + fl.y);
}

/* ============ fp16x3 GEMM kernel (mma.sync m16n8k16) ======================
   256 threads, 128x128 CTA tile (warp grid 2x4, 64x32 per warp).
   32-k chunks, 3 SMEM stages, ONE barrier per chunk, 2-chunk prefetch.
   Stage: Ahi(8K) Alo(8K) Bhi(8K) Blo(8K) = 32KB; 3 stages = 96KB.
   Rows are 64B (4x16B segs); swizzle seg' = seg ^ ((row>>1)&3).
   2 CTAs/SM (regs capped at 128 by launch_bounds).                         */
#define A_PLANE 8192
#define B_PLANE 8192
#define STAGE_B 32768
#define SMEM_DYN (3*STAGE_B)   /* 98304 */

__global__ __launch_bounds__(256, 2) void tc_kernel(
    int mode, int s, int flip, const float* __restrict__ lam)
{
    extern __shared__ char smem[];
    const uint32_t smem_u = smem_u32(smem);

    const int tid = threadIdx.x;
    const int wid = tid >> 5, lane = tid & 31;
    const int gid = lane >> 2, tig = lane & 3;
    const int m = lane >> 3, l7 = lane & 7;
    const int warpM = wid >> 2, warpN = wid & 3;   /* 2 x 4 warps */
    const int rowBase = warpM * 64, colBase = warpN * 32;

    int row0, col0;
    if (mode == 1) {
        int x = blockIdx.x, ti = 0;
        while ((ti + 1) * (ti + 2) / 2 <= x) ti++;
        int tj = x - ti * (ti + 1) / 2;
        row0 = ti * 128; col0 = tj * 128;
    } else {
        row0 = blockIdx.y * 128; col0 = blockIdx.x * 128;
    }

    const half *Ahi, *Alo, *Bhi, *Blo; int K;
    if (mode == 0) {
        Ahi = flip ? g_Shi1 : g_Shi0; Alo = flip ? g_Slo1 : g_Slo0;
        Bhi = g_Whi; Blo = g_Wlo; K = RES;
    } else if (mode == 1) {
        size_t base = (size_t)blockIdx.z * TLEN * RES;
        Ahi = g_rshi + base; Alo = g_rslo + base;
        Bhi = Ahi; Blo = Alo; K = RES;
    } else {
        Ahi = g_xhi; Alo = g_xlo; Bhi = g_WinHi; Blo = g_WinLo; K = INDIM;
    }
    const int nIter = K >> 5;   /* 32-k chunks */

    float acc[4][4][4] = {};

    /* per-lane LDSM address components */
    uint32_t aRB[4], aX[4], bRB[2], bX[2];
    #pragma unroll
    for (int mt = 0; mt < 4; mt++) {
        uint32_t r = rowBase + mt * 16 + (m & 1) * 8 + l7;
        aRB[mt] = r * 64; aX[mt] = (r >> 1) & 3;
    }
    #pragma unroll
    for (int np = 0; np < 2; np++) {
        uint32_t n = colBase + (np * 2 + (m >> 1)) * 8 + l7;
        bRB[np] = n * 64; bX[np] = (n >> 1) & 3;
    }
    const uint32_t amk = (uint32_t)(m >> 1);
    const uint32_t bmk = (uint32_t)(m & 1);

    /* ---- loader: 2048 16B segs per 32-k chunk, 8 per thread ---- */
    auto load_chunk = [&](int it, int stage) {
        const int k0 = it << 5;
        const uint32_t sb = smem_u + (uint32_t)stage * STAGE_B;
        #pragma unroll
        for (int q = 0; q < 8; q++) {
            int idx = tid + q * 256;
            int op = idx >> 10;                /* 0: A planes, 1: B planes */
            int j = idx & 1023;
            int p = j >> 9, r = (j >> 2) & 127, c = j & 3;
            const half* gp = op ? (p ? Blo : Bhi) : (p ? Alo : Ahi);
            int rowg = (op ? col0 : row0) + r;
            const half* src = gp + (size_t)rowg * K + k0 + c * 8;
            uint32_t dst = sb + (uint32_t)op * (2 * A_PLANE) + (uint32_t)p * A_PLANE
                         + (uint32_t)r * 64 + (uint32_t)((c ^ ((r >> 1) & 3)) * 16);
            cpasync16(dst, src);
        }
    };

    load_chunk(0, 0);
    cp_commit();
    if (nIter > 1) { load_chunk(1, 1); cp_commit(); }

    for (int it = 0; it < nIter; ++it) {
        if (it + 1 < nIter) cp_wait1(); else cp_wait0();
        __syncthreads();
        if (it + 2 < nIter) { load_chunk(it + 2, (it + 2) % 3); cp_commit(); }

        const uint32_t sb = smem_u + (uint32_t)(it % 3) * STAGE_B;
        const uint32_t pAh = sb, pAl = sb + A_PLANE;
        const uint32_t pBh = sb + 2 * A_PLANE, pBl = pBh + B_PLANE;
        #pragma unroll
        for (int h16 = 0; h16 < 2; h16++) {
            uint32_t bh[2][4], bl[2][4];
            #pragma unroll
            for (int np = 0; np < 2; np++) {
                uint32_t off = bRB[np] + (((h16 * 2 + bmk) ^ bX[np]) * 16);
                ldsm4(bh[np], pBh + off);
                ldsm4(bl[np], pBl + off);
            }
            #pragma unroll
            for (int mt = 0; mt < 4; mt++) {
                uint32_t ah[4], al[4];
                uint32_t off = aRB[mt] + (((h16 * 2 + amk) ^ aX[mt]) * 16);
                ldsm4(ah, pAh + off);
                ldsm4(al, pAl + off);
                #pragma unroll
                for (int nt = 0; nt < 4; nt++) {
                    uint32_t b0h = bh[nt >> 1][(nt & 1) * 2], b1h = bh[nt >> 1][(nt & 1) * 2 + 1];
                    uint32_t b0l = bl[nt >> 1][(nt & 1) * 2], b1l = bl[nt >> 1][(nt & 1) * 2 + 1];
                    mma16816(acc[mt][nt], ah, b0h, b1h);
                    mma16816(acc[mt][nt], ah, b0l, b1l);
                    mma16816(acc[mt][nt], al, b0h, b1h);
                }
            }
        }
    }

    /* -------------------- epilogue (register -> global, planes only) ------- */
    float regc = 0.f;
    if (mode == 1) { float l = lam[0]; regc = log1pf(expf(l)); }
    const half* SoHi = flip ? g_Shi1 : g_Shi0;
    const half* SoLo = flip ? g_Slo1 : g_Slo0;
    half* ShiN = flip ? g_Shi0 : g_Shi1;
    half* SloN = flip ? g_Slo0 : g_Slo1;

    #pragma unroll
    for (int mt = 0; mt < 4; mt++)
        #pragma unroll
        for (int nt = 0; nt < 4; nt++)
            #pragma unroll
            for (int h = 0; h < 2; h++) {
                int grow = row0 + rowBase + mt * 16 + gid + h * 8;
                int col = col0 + colBase + nt * 8 + tig * 2;
                float cx = acc[mt][nt][h * 2 + 0];
                float cy = acc[mt][nt][h * 2 + 1];
                if (mode == 0) {
                    int b = grow >> 7, w = grow & 127;
                    int t = 4 * w + s - 2;
                    size_t so_off = (size_t)grow * RES + col;
                    float2 so = rec2(*(const half2*)&SoHi[so_off],
                                     *(const half2*)&SoLo[so_off]);
                    float2 u = make_float2(0.f, 0.f);
                    if (t >= 0) {
                        size_t uo = ((size_t)(b << 9) + t) * RES + col;
                        u = rec2(*(const half2*)&g_iphi[uo], *(const half2*)&g_iplo[uo]);
                    }
                    float2 v;
                    v.x = 0.7f * so.x + 0.3f * sinf(cx + u.x);
                    v.y = 0.7f * so.y + 0.3f * sinf(cy + u.y);
                    half hx, lx, hy, ly;
                    split16(v.x, hx, lx); split16(v.y, hy, ly);
                    *(half2*)&ShiN[so_off] = __halves2half2(hx, hy);
                    *(half2*)&SloN[so_off] = __halves2half2(lx, ly);
                    if (s >= 2) {
                        size_t ro = ((size_t)(b << 9) + t) * RES + col;
                        *(half2*)&g_rshi[ro] = __halves2half2(hx, hy);
                        *(half2*)&g_rslo[ro] = __halves2half2(lx, ly);
                    }
                } else if (mode == 1) {
                    float* Abm = g_A + (size_t)blockIdx.z * TLEN * TLEN;
                    float2 v;
                    v.x = cx + 1.0f + ((grow == col + 0) ? regc : 0.f);
                    v.y = cy + 1.0f + ((grow == col + 1) ? regc : 0.f);
                    *(float2*)&Abm[(size_t)grow * TLEN + col] = v;
                } else {
                    half hx, lx, hy, ly;
                    split16(cx, hx, lx); split16(cy, hy, ly);
                    size_t off = (size_t)grow * RES + col;
                    *(half2*)&g_iphi[off] = __halves2half2(hx, hy);
                    *(half2*)&g_iplo[off] = __halves2half2(lx, ly);
                }
            }
}

/* ============ split+transpose weights: dst[c][r] = split(src[r][c]) ======= */
__global__ void split_trans_kernel(const float* __restrict__ src, int rows, int cols, int which)
{
    half* dh = which ? g_WinHi : g_Whi;
    half* dl = which ? g_WinLo : g_Wlo;
    __shared__ float t[32][33];
    int c0 = blockIdx.x * 32, r0 = blockIdx.y * 32;
    for (int j = threadIdx.y; j < 32; j += 8)
        t[j][threadIdx.x] = src[(size_t)(r0 + j) * cols + c0 + threadIdx.x];
    __syncthreads();
    for (int j = threadIdx.y; j < 32; j += 8) {
        float f = t[threadIdx.x][j];
        half h, l; split16(f, h, l);
        size_t o = (size_t)(c0 + j) * rows + r0 + threadIdx.x;
        dh[o] = h; dl[o] = l;
    }
}

/* ============ split input rows (no transpose) ============================= */
__global__ void split_input_kernel(const float* __restrict__ src)
{
    int idx = blockIdx.x * 256 + threadIdx.x;
    float f = src[idx];
    half h, l; split16(f, h, l);
    g_xhi[idx] = h; g_xlo[idx] = l;
}

/* =================== step s=0 (state was zero), half2-wide ================ */
__global__ __launch_bounds__(256) void init0_kernel()
{
    int idx = blockIdx.x * 256 + threadIdx.x;   /* over MROWS*RES/2 */
    int row = idx >> 10, q2 = (idx & 1023) * 2;
    int b = row >> 7, w = row & 127;
    int t = 4 * w - 2;
    half2 ph = __float2half2_rn(0.f), pl = ph;
    if (t >= 0) {
        size_t uo = ((size_t)(b << 9) + t) * RES + q2;
        float2 u = rec2(*(const half2*)&g_iphi[uo], *(const half2*)&g_iplo[uo]);
        float vx = 0.3f * sinf(u.x), vy = 0.3f * sinf(u.y);
        half hx, lx, hy, ly;
        split16(vx, hx, lx); split16(vy, hy, ly);
        ph = __halves2half2(hx, hy); pl = __halves2half2(lx, ly);
    }
    size_t so = (size_t)row * RES + q2;
    *(half2*)&g_Shi0[so] = ph;
    *(half2*)&g_Slo0[so] = pl;
}

/* ====== transpose Cholesky factors: g_LT[b][j][i] = g_A[b][i][j] ========== */
__global__ void transL_kernel()
{
    const int b = blockIdx.z;
    const float* src = g_A + (size_t)b * TLEN * TLEN;
    float* dst = g_LT + (size_t)b * TLEN * TLEN;
    __shared__ float t[32][33];
    int c0 = blockIdx.x * 32, r0 = blockIdx.y * 32;
    for (int j = threadIdx.y; j < 32; j += 8)
        t[j][threadIdx.x] = src[(size_t)(r0 + j) * TLEN + c0 + threadIdx.x];
    __syncthreads();
    for (int j = threadIdx.y; j < 32; j += 8)
        dst[(size_t)(c0 + j) * TLEN + r0 + threadIdx.x] = t[threadIdx.x][j];
}

/* ============ blocked Cholesky, NB=64 ===================================== */
__global__ __launch_bounds__(256) void chol_panel_kernel(int p)
{
    const int b = blockIdx.x;
    float* Ab = g_A + (size_t)b * TLEN * TLEN;
    const int jb = p * 64;
    __shared__ float L11[64][65];
    const int tid = threadIdx.x;
    for (int idx = tid; idx < 64 * 64; idx += 256) {
        int r = idx >> 6, c = idx & 63;
        L11[r][c] = Ab[(jb + r) * TLEN + jb + c];
    }
    __syncthreads();
    for (int k = 0; k < 64; k++) {
        if (tid == 0) L11[k][k] = sqrtf(L11[k][k]);
        __syncthreads();
        if (tid > k && tid < 64) L11[tid][k] /= L11[k][k];
        __syncthreads();
        for (int idx = tid; idx < 64 * 64; idx += 256) {
            int r = idx >> 6, c = idx & 63;
            if (r > k && c > k && c <= r) L11[r][c] -= L11[r][k] * L11[c][k];
        }
        __syncthreads();
    }
    for (int idx = tid; idx < 64 * 64; idx += 256) {
        int r = idx >> 6, c = idx & 63;
        if (c <= r) Ab[(jb + r) * TLEN + jb + c] = L11[r][c];
    }
    __syncthreads();
    const int mrows = TLEN - jb - 64;
    for (int r = tid; r < mrows; r += 256) {
        int i = jb + 64 + r;
        float a[64];
        #pragma unroll
        for (int c = 0; c < 64; c++) a[c] = Ab[i * TLEN + jb + c];
        #pragma unroll
        for (int k = 0; k < 64; k++) {
            float sv = a[k];
            #pragma unroll
            for (int q = 0; q < k; q++) sv -= a[q] * L11[k][q];
            a[k] = sv / L11[k][k];
        }
        #pragma unroll
        for (int c = 0; c < 64; c++) Ab[i * TLEN + jb + c] = a[c];
    }
}

__global__ __launch_bounds__(256) void chol_update_kernel(int p)
{
    const int jb = p * 64 + 64;
    int idx = blockIdx.x;
    int ti = 0;
    while ((ti + 1) * (ti + 2) / 2 <= idx) ti++;
    int tj = idx - ti * (ti + 1) / 2;
    const int b = blockIdx.y;
    float* Ab = g_A + (size_t)b * TLEN * TLEN;
    const int r0 = jb + ti * 64, c0 = jb + tj * 64;
    __shared__ float La[64][65], Lb[64][65];
    const int tid = threadIdx.x;
    for (int q = tid; q < 64 * 64; q += 256) {
        int r = q >> 6, c = q & 63;
        La[r][c] = Ab[(r0 + r) * TLEN + p * 64 + c];
        Lb[r][c] = Ab[(c0 + r) * TLEN + p * 64 + c];
    }
    __syncthreads();
    const int tx = tid & 15, ty = tid >> 4;
    float acc[4][4] = {};
    #pragma unroll
    for (int k = 0; k < 64; k++) {
        float ar[4], bc[4];
        #pragma unroll
        for (int i = 0; i < 4; i++) ar[i] = La[ty * 4 + i][k];
        #pragma unroll
        for (int j = 0; j < 4; j++) bc[j] = Lb[tx * 4 + j][k];
        #pragma unroll
        for (int i = 0; i < 4; i++)
            #pragma unroll
            for (int j = 0; j < 4; j++)
                acc[i][j] += ar[i] * bc[j];
    }
    #pragma unroll
    for (int i = 0; i < 4; i++)
        #pragma unroll
        for (int j = 0; j < 4; j++)
            Ab[(r0 + ty * 4 + i) * TLEN + c0 + tx * 4 + j] -= acc[i][j];
}

/* ============ triangular solves, 64 RHS in registers ====================== */
__global__ __launch_bounds__(512) void solve_kernel(const float* __restrict__ Y)
{
    const int b = blockIdx.x;
    const int i = threadIdx.x;
    const float* __restrict__ Ab = g_A + (size_t)b * TLEN * TLEN;
    const float* __restrict__ Lt = g_LT + (size_t)b * TLEN * TLEN;
    float acc[OUTD];
    #pragma unroll
    for (int o = 0; o < OUTD; o++) acc[o] = Y[((size_t)b * TLEN + i) * OUTD + o];
    __shared__ float zrow[OUTD];
    for (int j = 0; j < TLEN; j++) {
        if (i == j) {
            float dinv = 1.f / Ab[j * TLEN + j];
            #pragma unroll
            for (int o = 0; o < OUTD; o++) { acc[o] *= dinv; zrow[o] = acc[o]; }
        }
        __syncthreads();
        if (i > j) {
            float lij = Lt[j * TLEN + i];
            #pragma unroll
            for (int o = 0; o < OUTD; o++) acc[o] -= lij * zrow[o];
        }
        __syncthreads();
    }
    for (int j = TLEN - 1; j >= 0; j--) {
        if (i == j) {
            float dinv = 1.f / Ab[j * TLEN + j];
            #pragma unroll
            for (int o = 0; o < OUTD; o++) { acc[o] *= dinv; zrow[o] = acc[o]; }
        }
        __syncthreads();
        if (i < j) {
            float lji = Ab[j * TLEN + i];
            #pragma unroll
            for (int o = 0; o < OUTD; o++) acc[o] -= lji * zrow[o];
        }
        __syncthreads();
    }
    #pragma unroll
    for (int o = 0; o < OUTD; o++) g_Z[((size_t)b * TLEN + i) * OUTD + o] = acc[o];
}

/* ============ W = Xb^T Z  (2048 x 64, K=512), X from rs planes ============ */
__global__ __launch_bounds__(256) void wout_kernel(float* __restrict__ out)
{
    const int b = blockIdx.y;
    const half* __restrict__ Xh = g_rshi + (size_t)b * TLEN * RES;
    const half* __restrict__ Xl = g_rslo + (size_t)b * TLEN * RES;
    const float* __restrict__ Zb = g_Z + (size_t)b * TLEN * OUTD;
    const int d0 = blockIdx.x * 128;
    __shared__ float As2[16][132];
    __shared__ float Bs2[16][68];
    const int tid = threadIdx.x;
    const int lr = tid >> 4, lc = (tid & 15) * 4;
    const int ty = tid >> 4, tx = tid & 15;
    float acc[8][4] = {};
    for (int k0 = 0; k0 < TLEN; k0 += 16) {
        #pragma unroll
        for (int half64 = 0; half64 < 2; half64++) {
            size_t off = (size_t)(k0 + lr) * RES + d0 + lc + half64 * 64;
            half2 h0 = *(const half2*)&Xh[off],     h1 = *(const half2*)&Xh[off + 2];
            half2 l0 = *(const half2*)&Xl[off],     l1 = *(const half2*)&Xl[off + 2];
            float2 a0 = rec2(h0, l0), a1 = rec2(h1, l1);
            As2[lr][lc + half64 * 64 + 0] = a0.x;
            As2[lr][lc + half64 * 64 + 1] = a0.y;
            As2[lr][lc + half64 * 64 + 2] = a1.x;
            As2[lr][lc + half64 * 64 + 3] = a1.y;
        }
        *(float4*)&Bs2[lr][lc] = *(const float4*)&Zb[(k0 + lr) * OUTD + lc];
        __syncthreads();
        #pragma unroll
        for (int k = 0; k < 16; k++) {
            float fa[8], fb[4];
            *(float4*)&fa[0] = *(const float4*)&As2[k][ty * 8];
            *(float4*)&fa[4] = *(const float4*)&As2[k][ty * 8 + 4];
            *(float4*)&fb[0] = *(const float4*)&Bs2[k][tx * 4];
            #pragma unroll
            for (int i = 0; i < 8; i++)
                #pragma unroll
                for (int j = 0; j < 4; j++)
                    acc[i][j] += fa[i] * fb[j];
        }
        __syncthreads();
    }
    #pragma unroll
    for (int i = 0; i < 8; i++)
        #pragma unroll
        for (int j = 0; j < 4; j++)
            out[((size_t)b * RES + d0 + ty * 8 + i) * OUTD + tx * 4 + j] = acc[i][j];
}

__global__ void bias_kernel(float* __restrict__ out)
{
    const int b = blockIdx.x, o = threadIdx.x;
    float s = 0.f;
    for (int n = 0; n < TLEN; n++) s += g_Z[((size_t)b * TLEN + n) * OUTD + o];
    out[(size_t)BATCH * RES * OUTD + b * OUTD + o] = s;
}

/* ======================= launch ======================= */
extern "C" void kernel_launch(void* const* d_in, const int* in_sizes, int n_in,
                              void* d_out, int out_size)
{
    const float* input  = (const float*)d_in[0];
    const float* target = (const float*)d_in[1];
    const float* W_res  = (const float*)d_in[2];
    const float* W_in   = (const float*)d_in[3];
    const float* lam    = (const float*)d_in[4];
    float* out = (float*)d_out;

    cudaFuncSetAttribute(tc_kernel, cudaFuncAttributeMaxDynamicSharedMemorySize, SMEM_DYN);

    /* 0. split+transpose weights, split input */
    split_trans_kernel<<<dim3(RES / 32, RES / 32), dim3(32, 8)>>>(W_res, RES, RES, 0);
    split_trans_kernel<<<dim3(RES / 32, INDIM / 32), dim3(32, 8)>>>(W_in, INDIM, RES, 1);
    split_input_kernel<<<(NROWS * INDIM) / 256, 256>>>(input);

    /* 1. input projection (writes inproj planes) */
    tc_kernel<<<dim3(RES / 128, NROWS / 128), 256, SMEM_DYN>>>(2, 0, 0, nullptr);

    /* 2. reservoir (state lives only as hi/lo planes) */
    init0_kernel<<<(MROWS * RES / 2) / 256, 256>>>();
    int flip = 0;
    for (int s = 1; s <= 5; s++) {
        tc_kernel<<<dim3(RES / 128, MROWS / 128), 256, SMEM_DYN>>>(0, s, flip, nullptr);
        flip ^= 1;
    }

    /* 3. gram: 10 lower (128x128) tiles; upper triangle never read */
    tc_kernel<<<dim3(10, 1, BATCH), 256, SMEM_DYN>>>(1, 0, 0, lam);

    /* 4. batched blocked Cholesky */
    for (int p = 0; p < 8; p++) {
        chol_panel_kernel<<<BATCH, 256>>>(p);
        if (p < 7) {
            int mt = 7 - p;
            chol_update_kernel<<<dim3(mt * (mt + 1) / 2, BATCH), 256>>>(p);
        }
    }

    /* 4b. transpose L for coalesced forward solve */
    transL_kernel<<<dim3(16, 16, BATCH), dim3(32, 8)>>>();

    /* 5. triangular solves */
    solve_kernel<<<BATCH, 512>>>(target);

    /* 6. readout */
    wout_kernel<<<dim3(RES / 128, BATCH), 256>>>(out);
    bias_kernel<<<BATCH, 64>>>(out);

    (void)in_sizes; (void)n_in; (void)out_size;
}